// round 4
// baseline (speedup 1.0000x reference)
#include <cuda_runtime.h>
#include <cuda_fp16.h>
#include <cstdint>

#define NR 8192
#define DD 256

// ---------------- device scratch (allocation-free) ----------------
__device__ __align__(256) __half g_Xhi[NR * DD], g_Xlo[NR * DD];
__device__ __align__(256) __half g_XThi[DD * NR], g_XTlo[DD * NR];
__device__ __align__(256) __half g_RThi[DD * DD], g_RTlo[DD * DD];
__device__ __align__(256) __half g_EThi[DD * DD], g_ETlo[DD * DD];
__device__ __align__(256) __half g_Qhi[NR * DD], g_Qlo[NR * DD];
__device__ __align__(256) __half g_Khi[NR * DD], g_Klo[NR * DD];
__device__ __align__(256) float  g_L[(size_t)NR * NR];
__device__ __align__(256) __half g_Phi[(size_t)NR * NR];
__device__ __align__(256) __half g_Plo[(size_t)NR * NR];

// ---------------- PTX helpers (all plain-sm_100-safe: sm_80 era) ----------------
__device__ __forceinline__ uint32_t s2u(const void* p) {
    uint32_t a;
    asm("{ .reg .u64 t; cvta.to.shared.u64 t, %1; cvt.u32.u64 %0, t; }" : "=r"(a) : "l"(p));
    return a;
}
__device__ __forceinline__ void cpasync16(uint32_t dst, const void* src) {
    asm volatile("cp.async.cg.shared.global [%0], [%1], 16;" :: "r"(dst), "l"(src));
}
__device__ __forceinline__ void cp_commit() {
    asm volatile("cp.async.commit_group;" ::: "memory");
}
template <int N>
__device__ __forceinline__ void cp_wait() {
    asm volatile("cp.async.wait_group %0;" :: "n"(N) : "memory");
}
__device__ __forceinline__ void ldsm4(uint32_t* r, uint32_t a) {
    asm volatile("ldmatrix.sync.aligned.m8n8.x4.shared.b16 {%0,%1,%2,%3}, [%4];"
                 : "=r"(r[0]), "=r"(r[1]), "=r"(r[2]), "=r"(r[3]) : "r"(a));
}
__device__ __forceinline__ void mma16816(float* d, const uint32_t* a, const uint32_t* b) {
    asm volatile(
        "mma.sync.aligned.m16n8k16.row.col.f32.f16.f16.f32 "
        "{%0,%1,%2,%3}, {%4,%5,%6,%7}, {%8,%9}, {%0,%1,%2,%3};"
        : "+f"(d[0]), "+f"(d[1]), "+f"(d[2]), "+f"(d[3])
        : "r"(a[0]), "r"(a[1]), "r"(a[2]), "r"(a[3]), "r"(b[0]), "r"(b[1]));
}

// ---------------- prep kernels: fp16 hi/lo split ----------------
__global__ void __launch_bounds__(256) prep_params(const float* __restrict__ R,
                                                   const float* __restrict__ E) {
    int idx = blockIdx.x * 256 + threadIdx.x;   // 65536
    int k = idx >> 8, j = idx & 255;
    float r = R[idx] * 0.0625f;                 // fold 1/sqrt(d) = 1/16 into rotation
    __half h = __float2half_rn(r);
    g_RThi[j * DD + k] = h;
    g_RTlo[j * DD + k] = __float2half_rn(r - __half2float(h));
    float e = E[idx];
    h = __float2half_rn(e);
    g_EThi[j * DD + k] = h;
    g_ETlo[j * DD + k] = __float2half_rn(e - __half2float(h));
}

__global__ void __launch_bounds__(256) prep_x(const float* __restrict__ X) {
    int idx = blockIdx.x * 256 + threadIdx.x;   // 2M
    int r = idx >> 8, c = idx & 255;
    float v = X[idx];
    __half h = __float2half_rn(v);
    __half l = __float2half_rn(v - __half2float(h));
    g_Xhi[idx] = h;
    g_Xlo[idx] = l;
    g_XThi[(size_t)c * NR + r] = h;
    g_XTlo[(size_t)c * NR + r] = l;
}

// ---------------- split-fp16 GEMM: C = A @ B^T ----------------
// A: [M,K] hi/lo fp16 row-major. B: [Ncols,K] hi/lo fp16 row-major.
// CTA tile 128x128, BK=64, 256 threads (8 warps, 4m x 2n, 32x64 each).
// Accumulate Ahi*Bhi + Ahi*Blo + Alo*Bhi in fp32.
// mode 0: write split fp16 (Chi/Clo). mode 1: write fp32 (Cf).
#define TILE_B 16384      // one 128x64 fp16 tile
#define STAGE_B 65536     // 4 tiles per stage

__device__ __forceinline__ void load_stage(char* st, const __half* const* gA,
                                           int kc, int K, int tid) {
    #pragma unroll
    for (int t = 0; t < 4; ++t) {
        const __half* src = gA[t] + kc;
        uint32_t dst = s2u(st + t * TILE_B);
        #pragma unroll
        for (int i = 0; i < 4; ++i) {
            int id = tid + i * 256;
            int r = id >> 3, cc = id & 7;
            uint32_t off = (uint32_t)(r * 128) + (uint32_t)((cc ^ (r & 7)) << 4);
            cpasync16(dst + off, src + (size_t)r * K + cc * 8);
        }
    }
    cp_commit();
}

__device__ __forceinline__ void compute_stage(char* st, float acc[2][8][4],
                                              int lane, int wm, int wn) {
    const uint32_t bAh = s2u(st);
    const uint32_t bAl = bAh + TILE_B;
    const uint32_t bBh = bAh + 2 * TILE_B;
    const uint32_t bBl = bAh + 3 * TILE_B;
    #pragma unroll
    for (int k16 = 0; k16 < 4; ++k16) {
        uint32_t ah[2][4], al[2][4], bh[4][4], bl[4][4];
        #pragma unroll
        for (int mt = 0; mt < 2; ++mt) {
            int row = wm * 32 + mt * 16 + (lane & 15);
            int c = k16 * 2 + (lane >> 4);
            uint32_t off = (uint32_t)(row * 128) + (uint32_t)((c ^ (row & 7)) << 4);
            ldsm4(ah[mt], bAh + off);
            ldsm4(al[mt], bAl + off);
        }
        #pragma unroll
        for (int p = 0; p < 4; ++p) {
            int n = wn * 64 + p * 16 + ((lane >> 4) << 3) + (lane & 7);
            int c = k16 * 2 + ((lane >> 3) & 1);
            uint32_t off = (uint32_t)(n * 128) + (uint32_t)((c ^ (n & 7)) << 4);
            ldsm4(bh[p], bBh + off);
            ldsm4(bl[p], bBl + off);
        }
        #pragma unroll
        for (int mt = 0; mt < 2; ++mt) {
            #pragma unroll
            for (int p = 0; p < 4; ++p) {
                mma16816(acc[mt][2 * p + 0], ah[mt], &bh[p][0]);
                mma16816(acc[mt][2 * p + 1], ah[mt], &bh[p][2]);
                mma16816(acc[mt][2 * p + 0], al[mt], &bh[p][0]);
                mma16816(acc[mt][2 * p + 1], al[mt], &bh[p][2]);
                mma16816(acc[mt][2 * p + 0], ah[mt], &bl[p][0]);
                mma16816(acc[mt][2 * p + 1], ah[mt], &bl[p][2]);
            }
        }
    }
}

__global__ void __launch_bounds__(256, 1) gemm_tn(
    const __half* __restrict__ Ahi, const __half* __restrict__ Alo,
    const __half* __restrict__ Bhi, const __half* __restrict__ Blo,
    int K, int mode, float* __restrict__ Cf,
    __half* __restrict__ Chi, __half* __restrict__ Clo, int ldc) {
    extern __shared__ char sm[];
    const int tid = threadIdx.x, lane = tid & 31, wid = tid >> 5;
    const int wm = wid & 3, wn = wid >> 2;
    const int rowA = blockIdx.y * 128, colB = blockIdx.x * 128;

    const __half* gA[4] = {
        Ahi + (size_t)rowA * K, Alo + (size_t)rowA * K,
        Bhi + (size_t)colB * K, Blo + (size_t)colB * K };

    float acc[2][8][4];
    #pragma unroll
    for (int a = 0; a < 2; ++a)
        #pragma unroll
        for (int b = 0; b < 8; ++b)
            #pragma unroll
            for (int c = 0; c < 4; ++c) acc[a][b][c] = 0.f;

    const int NC = K >> 6;
    load_stage(sm, gA, 0, K, tid);
    load_stage(sm + STAGE_B, gA, 64, K, tid);

    for (int c = 0; c < NC; ++c) {
        if (c + 1 < NC) cp_wait<1>(); else cp_wait<0>();
        __syncthreads();
        compute_stage(sm + (c & 1) * STAGE_B, acc, lane, wm, wn);
        if (c + 2 < NC) {
            __syncthreads();
            load_stage(sm + (c & 1) * STAGE_B, gA, (c + 2) * 64, K, tid);
        }
    }

    // epilogue
    const int quad = lane >> 2, tc = lane & 3;
    #pragma unroll
    for (int mt = 0; mt < 2; ++mt) {
        #pragma unroll
        for (int h = 0; h < 2; ++h) {
            const int row = rowA + wm * 32 + mt * 16 + quad + h * 8;
            #pragma unroll
            for (int nt = 0; nt < 8; ++nt) {
                const int col = colB + wn * 64 + nt * 8 + tc * 2;
                float v0 = acc[mt][nt][h * 2 + 0];
                float v1 = acc[mt][nt][h * 2 + 1];
                if (mode == 1) {
                    float2 w = make_float2(v0, v1);
                    *(float2*)(Cf + (size_t)row * ldc + col) = w;
                } else {
                    __half h0 = __float2half_rn(v0), h1 = __float2half_rn(v1);
                    __half l0 = __float2half_rn(v0 - __half2float(h0));
                    __half l1 = __float2half_rn(v1 - __half2float(h1));
                    *(__half2*)(Chi + (size_t)row * ldc + col) = __halves2half2(h0, h1);
                    *(__half2*)(Clo + (size_t)row * ldc + col) = __halves2half2(l0, l1);
                }
            }
        }
    }
}

// ---------------- row softmax: P = softmax(L), split fp16 ----------------
__global__ void __launch_bounds__(256) softmax_k() {
    __shared__ float red[256];
    const int row = blockIdx.x;
    const int t = threadIdx.x;
    const float* Lr = g_L + (size_t)row * NR;
    float v[32];
    float m = -3.4e38f;
    #pragma unroll
    for (int i = 0; i < 32; ++i) { v[i] = Lr[t + i * 256]; m = fmaxf(m, v[i]); }
    red[t] = m; __syncthreads();
    for (int s = 128; s > 0; s >>= 1) {
        if (t < s) red[t] = fmaxf(red[t], red[t + s]);
        __syncthreads();
    }
    m = red[0]; __syncthreads();
    float sum = 0.f;
    #pragma unroll
    for (int i = 0; i < 32; ++i) { v[i] = __expf(v[i] - m); sum += v[i]; }
    red[t] = sum; __syncthreads();
    for (int s = 128; s > 0; s >>= 1) {
        if (t < s) red[t] += red[t + s];
        __syncthreads();
    }
    const float inv = 1.0f / red[0];
    __half* ph = g_Phi + (size_t)row * NR;
    __half* pl = g_Plo + (size_t)row * NR;
    #pragma unroll
    for (int i = 0; i < 32; ++i) {
        float p = v[i] * inv;
        __half h = __float2half_rn(p);
        ph[t + i * 256] = h;
        pl[t + i * 256] = __float2half_rn(p - __half2float(h));
    }
}

// ---------------- launch ----------------
extern "C" void kernel_launch(void* const* d_in, const int* in_sizes, int n_in,
                              void* d_out, int out_size) {
    const float* R = (const float*)d_in[0];
    const float* E = (const float*)d_in[1];
    const float* X = (const float*)d_in[2];
    float* out = (float*)d_out;

    const int SMEM = 2 * STAGE_B;   // 128 KB
    cudaFuncSetAttribute(gemm_tn, cudaFuncAttributeMaxDynamicSharedMemorySize, SMEM);

    void *xhi, *xlo, *xthi, *xtlo, *rthi, *rtlo, *ethi, *etlo;
    void *qhi, *qlo, *khi, *klo, *lptr, *phi, *plo;
    cudaGetSymbolAddress(&xhi, g_Xhi);   cudaGetSymbolAddress(&xlo, g_Xlo);
    cudaGetSymbolAddress(&xthi, g_XThi); cudaGetSymbolAddress(&xtlo, g_XTlo);
    cudaGetSymbolAddress(&rthi, g_RThi); cudaGetSymbolAddress(&rtlo, g_RTlo);
    cudaGetSymbolAddress(&ethi, g_EThi); cudaGetSymbolAddress(&etlo, g_ETlo);
    cudaGetSymbolAddress(&qhi, g_Qhi);   cudaGetSymbolAddress(&qlo, g_Qlo);
    cudaGetSymbolAddress(&khi, g_Khi);   cudaGetSymbolAddress(&klo, g_Klo);
    cudaGetSymbolAddress(&lptr, g_L);
    cudaGetSymbolAddress(&phi, g_Phi);   cudaGetSymbolAddress(&plo, g_Plo);

    prep_params<<<DD * DD / 256, 256>>>(R, E);
    prep_x<<<NR, 256>>>(X);

    // Q = X @ (R/16)   (B = (R/16)^T, split out)
    gemm_tn<<<dim3(2, 64), 256, SMEM>>>((__half*)xhi, (__half*)xlo, (__half*)rthi, (__half*)rtlo,
                                        DD, 0, nullptr, (__half*)qhi, (__half*)qlo, DD);
    // K = X @ E        (split out)
    gemm_tn<<<dim3(2, 64), 256, SMEM>>>((__half*)xhi, (__half*)xlo, (__half*)ethi, (__half*)etlo,
                                        DD, 0, nullptr, (__half*)khi, (__half*)klo, DD);
    // L = Q @ K^T      (fp32 out; 1/16 already folded into Q)
    gemm_tn<<<dim3(64, 64), 256, SMEM>>>((__half*)qhi, (__half*)qlo, (__half*)khi, (__half*)klo,
                                         DD, 1, (float*)lptr, nullptr, nullptr, NR);
    // P = softmax(L)   (split out)
    softmax_k<<<NR, 256>>>();
    // O = P @ X        (B = X^T rows; fp32 out)
    gemm_tn<<<dim3(2, 64), 256, SMEM>>>((__half*)phi, (__half*)plo, (__half*)xthi, (__half*)xtlo,
                                        NR, 1, out, nullptr, nullptr, DD);
}

// round 5
// speedup vs baseline: 1.3317x; 1.3317x over previous
#include <cuda_runtime.h>
#include <cuda_fp16.h>
#include <cstdint>

#define NR 8192
#define DD 256

// ---------------- device scratch (allocation-free) ----------------
__device__ __align__(256) __half g_Xhi[NR * DD], g_Xlo[NR * DD];
__device__ __align__(256) __half g_XThi[DD * NR];
__device__ __align__(256) __half g_RThi[DD * DD], g_RTlo[DD * DD];
__device__ __align__(256) __half g_EThi[DD * DD], g_ETlo[DD * DD];
__device__ __align__(256) __half g_Qhi[NR * DD], g_Qlo[NR * DD];
__device__ __align__(256) __half g_Khi[NR * DD], g_Klo[NR * DD];
__device__ __align__(256) float  g_L[(size_t)NR * NR];
__device__ __align__(256) __half g_Phi[(size_t)NR * NR];

// ---------------- PTX helpers ----------------
__device__ __forceinline__ uint32_t s2u(const void* p) {
    uint32_t a;
    asm("{ .reg .u64 t; cvta.to.shared.u64 t, %1; cvt.u32.u64 %0, t; }" : "=r"(a) : "l"(p));
    return a;
}
__device__ __forceinline__ void cpasync16(uint32_t dst, const void* src) {
    asm volatile("cp.async.cg.shared.global [%0], [%1], 16;" :: "r"(dst), "l"(src));
}
__device__ __forceinline__ void cp_commit() {
    asm volatile("cp.async.commit_group;" ::: "memory");
}
template <int N>
__device__ __forceinline__ void cp_wait() {
    asm volatile("cp.async.wait_group %0;" :: "n"(N) : "memory");
}
__device__ __forceinline__ void ldsm4(uint32_t* r, uint32_t a) {
    asm volatile("ldmatrix.sync.aligned.m8n8.x4.shared.b16 {%0,%1,%2,%3}, [%4];"
                 : "=r"(r[0]), "=r"(r[1]), "=r"(r[2]), "=r"(r[3]) : "r"(a));
}
__device__ __forceinline__ void mma16816(float* d, const uint32_t* a, const uint32_t* b) {
    asm volatile(
        "mma.sync.aligned.m16n8k16.row.col.f32.f16.f16.f32 "
        "{%0,%1,%2,%3}, {%4,%5,%6,%7}, {%8,%9}, {%0,%1,%2,%3};"
        : "+f"(d[0]), "+f"(d[1]), "+f"(d[2]), "+f"(d[3])
        : "r"(a[0]), "r"(a[1]), "r"(a[2]), "r"(a[3]), "r"(b[0]), "r"(b[1]));
}

// ---------------- prep kernels: fp16 hi/lo split ----------------
__global__ void __launch_bounds__(256) prep_params(const float* __restrict__ R,
                                                   const float* __restrict__ E) {
    int idx = blockIdx.x * 256 + threadIdx.x;   // 65536
    int k = idx >> 8, j = idx & 255;
    float r = R[idx] * 0.0625f;                 // fold 1/sqrt(d)=1/16 into rotation
    __half h = __float2half_rn(r);
    g_RThi[j * DD + k] = h;
    g_RTlo[j * DD + k] = __float2half_rn(r - __half2float(h));
    float e = E[idx];
    h = __float2half_rn(e);
    g_EThi[j * DD + k] = h;
    g_ETlo[j * DD + k] = __float2half_rn(e - __half2float(h));
}

__global__ void __launch_bounds__(256) prep_x(const float* __restrict__ X) {
    int idx = blockIdx.x * 256 + threadIdx.x;   // 2M
    int r = idx >> 8, c = idx & 255;
    float v = X[idx];
    __half h = __float2half_rn(v);
    g_Xhi[idx] = h;
    g_Xlo[idx] = __float2half_rn(v - __half2float(h));
    g_XThi[(size_t)c * NR + r] = h;
}

// ---------------- split-fp16 GEMM: C = A @ B^T ----------------
// CTA tile 128x128, BK=64, 256 threads (8 warps, 4m x 2n, each 32x64).
// NPROD=3: Ahi*Bhi + Ahi*Blo + Alo*Bhi (fp32 acc), 4 smem tiles/stage.
// NPROD=1: Ahi*Bhi only, 2 smem tiles/stage.
// mode 0: write split fp16 (Chi/Clo). mode 1: write fp32 (Cf).
#define TILE_B 16384      // one 128x64 fp16 tile
#define NSTAGE 3

template <int NPROD>
__device__ __forceinline__ void load_stage(char* st, const __half* const* gA,
                                           int kc, int K, int tid) {
    constexpr int NT = (NPROD == 1) ? 2 : 4;
    #pragma unroll
    for (int t = 0; t < NT; ++t) {
        const __half* src = gA[t] + kc;
        uint32_t dst = s2u(st + t * TILE_B);
        #pragma unroll
        for (int i = 0; i < 4; ++i) {
            int id = tid + i * 256;
            int r = id >> 3, cc = id & 7;
            uint32_t off = (uint32_t)(r * 128) + (uint32_t)((cc ^ (r & 7)) << 4);
            cpasync16(dst + off, src + (size_t)r * K + cc * 8);
        }
    }
}

template <int NPROD>
__device__ __forceinline__ void compute_stage(char* st, float acc[2][8][4],
                                              int lane, int wm, int wn) {
    const uint32_t bAh = s2u(st);
    const uint32_t bAl = bAh + TILE_B;
    const uint32_t bBh = (NPROD == 1) ? (bAh + TILE_B) : (bAh + 2 * TILE_B);
    const uint32_t bBl = bAh + 3 * TILE_B;
    #pragma unroll
    for (int k16 = 0; k16 < 4; ++k16) {
        uint32_t ah[2][4], al[2][4], bh[4][4], bl[4][4];
        #pragma unroll
        for (int mt = 0; mt < 2; ++mt) {
            int row = wm * 32 + mt * 16 + (lane & 15);
            int c = k16 * 2 + (lane >> 4);
            uint32_t off = (uint32_t)(row * 128) + (uint32_t)((c ^ (row & 7)) << 4);
            ldsm4(ah[mt], bAh + off);
            if (NPROD >= 3) ldsm4(al[mt], bAl + off);
        }
        #pragma unroll
        for (int p = 0; p < 4; ++p) {
            int n = wn * 64 + p * 16 + ((lane >> 4) << 3) + (lane & 7);
            int c = k16 * 2 + ((lane >> 3) & 1);
            uint32_t off = (uint32_t)(n * 128) + (uint32_t)((c ^ (n & 7)) << 4);
            ldsm4(bh[p], bBh + off);
            if (NPROD >= 2) ldsm4(bl[p], bBl + off);
        }
        #pragma unroll
        for (int mt = 0; mt < 2; ++mt) {
            #pragma unroll
            for (int p = 0; p < 4; ++p) {
                mma16816(acc[mt][2 * p + 0], ah[mt], &bh[p][0]);
                mma16816(acc[mt][2 * p + 1], ah[mt], &bh[p][2]);
                if (NPROD >= 3) {
                    mma16816(acc[mt][2 * p + 0], al[mt], &bh[p][0]);
                    mma16816(acc[mt][2 * p + 1], al[mt], &bh[p][2]);
                }
                if (NPROD >= 2) {
                    mma16816(acc[mt][2 * p + 0], ah[mt], &bl[p][0]);
                    mma16816(acc[mt][2 * p + 1], ah[mt], &bl[p][2]);
                }
            }
        }
    }
}

template <int NPROD, int MAXCTA>
__global__ void __launch_bounds__(256, MAXCTA) gemm_tn(
    const __half* __restrict__ Ahi, const __half* __restrict__ Alo,
    const __half* __restrict__ Bhi, const __half* __restrict__ Blo,
    int K, int mode, float* __restrict__ Cf,
    __half* __restrict__ Chi, __half* __restrict__ Clo, int ldc) {
    extern __shared__ char sm[];
    constexpr int SB = ((NPROD == 1) ? 2 : 4) * TILE_B;
    const int tid = threadIdx.x, lane = tid & 31, wid = tid >> 5;
    const int wm = wid & 3, wn = wid >> 2;
    const int rowA = blockIdx.y * 128, colB = blockIdx.x * 128;

    const __half* gA[4] = {
        Ahi + (size_t)rowA * K, (NPROD == 1) ? (Bhi + (size_t)colB * K) : (Alo + (size_t)rowA * K),
        Bhi + (size_t)colB * K, Blo + (size_t)colB * K };

    float acc[2][8][4];
    #pragma unroll
    for (int a = 0; a < 2; ++a)
        #pragma unroll
        for (int b = 0; b < 8; ++b)
            #pragma unroll
            for (int c = 0; c < 4; ++c) acc[a][b][c] = 0.f;

    const int NC = K >> 6;
    #pragma unroll
    for (int s = 0; s < NSTAGE; ++s) {
        if (s < NC) load_stage<NPROD>(sm + s * SB, gA, s * 64, K, tid);
        cp_commit();
    }

    for (int c = 0; c < NC; ++c) {
        cp_wait<NSTAGE - 1>();
        __syncthreads();
        compute_stage<NPROD>(sm + (c % NSTAGE) * SB, acc, lane, wm, wn);
        __syncthreads();
        int nx = c + NSTAGE;
        if (nx < NC) load_stage<NPROD>(sm + (nx % NSTAGE) * SB, gA, nx * 64, K, tid);
        cp_commit();
    }

    // epilogue
    const int quad = lane >> 2, tc = lane & 3;
    #pragma unroll
    for (int mt = 0; mt < 2; ++mt) {
        #pragma unroll
        for (int h = 0; h < 2; ++h) {
            const int row = rowA + wm * 32 + mt * 16 + quad + h * 8;
            #pragma unroll
            for (int nt = 0; nt < 8; ++nt) {
                const int col = colB + wn * 64 + nt * 8 + tc * 2;
                float v0 = acc[mt][nt][h * 2 + 0];
                float v1 = acc[mt][nt][h * 2 + 1];
                if (mode == 1) {
                    *(float2*)(Cf + (size_t)row * ldc + col) = make_float2(v0, v1);
                } else {
                    __half h0 = __float2half_rn(v0), h1 = __float2half_rn(v1);
                    __half l0 = __float2half_rn(v0 - __half2float(h0));
                    __half l1 = __float2half_rn(v1 - __half2float(h1));
                    *(__half2*)(Chi + (size_t)row * ldc + col) = __halves2half2(h0, h1);
                    *(__half2*)(Clo + (size_t)row * ldc + col) = __halves2half2(l0, l1);
                }
            }
        }
    }
}

// ---------------- row softmax: Phi = fp16(softmax(L)) ----------------
__global__ void __launch_bounds__(256) softmax_k() {
    __shared__ float red[256];
    const int row = blockIdx.x;
    const int t = threadIdx.x;
    const float* Lr = g_L + (size_t)row * NR;
    float v[32];
    float m = -3.4e38f;
    #pragma unroll
    for (int i = 0; i < 32; ++i) { v[i] = Lr[t + i * 256]; m = fmaxf(m, v[i]); }
    red[t] = m; __syncthreads();
    for (int s = 128; s > 0; s >>= 1) {
        if (t < s) red[t] = fmaxf(red[t], red[t + s]);
        __syncthreads();
    }
    m = red[0]; __syncthreads();
    float sum = 0.f;
    #pragma unroll
    for (int i = 0; i < 32; ++i) { v[i] = __expf(v[i] - m); sum += v[i]; }
    red[t] = sum; __syncthreads();
    for (int s = 128; s > 0; s >>= 1) {
        if (t < s) red[t] += red[t + s];
        __syncthreads();
    }
    const float inv = 1.0f / red[0];
    __half* ph = g_Phi + (size_t)row * NR;
    #pragma unroll
    for (int i = 0; i < 32; ++i)
        ph[t + i * 256] = __float2half_rn(v[i] * inv);
}

// ---------------- launch ----------------
extern "C" void kernel_launch(void* const* d_in, const int* in_sizes, int n_in,
                              void* d_out, int out_size) {
    const float* R = (const float*)d_in[0];
    const float* E = (const float*)d_in[1];
    const float* X = (const float*)d_in[2];
    float* out = (float*)d_out;

    const int SMEM3 = NSTAGE * 4 * TILE_B;   // 192 KB
    const int SMEM1 = NSTAGE * 2 * TILE_B;   // 96 KB
    cudaFuncSetAttribute(gemm_tn<3, 1>, cudaFuncAttributeMaxDynamicSharedMemorySize, SMEM3);
    cudaFuncSetAttribute(gemm_tn<1, 2>, cudaFuncAttributeMaxDynamicSharedMemorySize, SMEM1);

    void *xhi, *xlo, *xthi, *rthi, *rtlo, *ethi, *etlo;
    void *qhi, *qlo, *khi, *klo, *lptr, *phi;
    cudaGetSymbolAddress(&xhi, g_Xhi);   cudaGetSymbolAddress(&xlo, g_Xlo);
    cudaGetSymbolAddress(&xthi, g_XThi);
    cudaGetSymbolAddress(&rthi, g_RThi); cudaGetSymbolAddress(&rtlo, g_RTlo);
    cudaGetSymbolAddress(&ethi, g_EThi); cudaGetSymbolAddress(&etlo, g_ETlo);
    cudaGetSymbolAddress(&qhi, g_Qhi);   cudaGetSymbolAddress(&qlo, g_Qlo);
    cudaGetSymbolAddress(&khi, g_Khi);   cudaGetSymbolAddress(&klo, g_Klo);
    cudaGetSymbolAddress(&lptr, g_L);
    cudaGetSymbolAddress(&phi, g_Phi);

    prep_params<<<DD * DD / 256, 256>>>(R, E);
    prep_x<<<NR, 256>>>(X);

    // Q = X @ (R/16)   (split out)
    gemm_tn<3, 1><<<dim3(2, 64), 256, SMEM3>>>((__half*)xhi, (__half*)xlo, (__half*)rthi, (__half*)rtlo,
                                               DD, 0, nullptr, (__half*)qhi, (__half*)qlo, DD);
    // K = X @ E        (split out)
    gemm_tn<3, 1><<<dim3(2, 64), 256, SMEM3>>>((__half*)xhi, (__half*)xlo, (__half*)ethi, (__half*)etlo,
                                               DD, 0, nullptr, (__half*)khi, (__half*)klo, DD);
    // L = Q @ K^T      (fp32 out)
    gemm_tn<3, 1><<<dim3(64, 64), 256, SMEM3>>>((__half*)qhi, (__half*)qlo, (__half*)khi, (__half*)klo,
                                                DD, 1, (float*)lptr, nullptr, nullptr, NR);
    // P = softmax(L)   (fp16 hi only)
    softmax_k<<<NR, 256>>>();
    // O = P @ X        (single-product fp16, fp32 out)
    gemm_tn<1, 2><<<dim3(2, 64), 256, SMEM1>>>((__half*)phi, nullptr, (__half*)xthi, nullptr,
                                               NR, 1, out, nullptr, nullptr, DD);
}

// round 6
// speedup vs baseline: 1.3824x; 1.0381x over previous
#include <cuda_runtime.h>
#include <cuda_fp16.h>
#include <cstdint>

#define NR 8192
#define DD 256

// ---------------- device scratch (allocation-free) ----------------
__device__ __align__(256) __half g_Xhi[NR * DD], g_Xlo[NR * DD];
__device__ __align__(256) __half g_XThi[DD * NR];
__device__ __align__(256) __half g_Whi[512 * DD], g_Wlo[512 * DD];     // [Rt/16 ; Et]
__device__ __align__(256) __half g_QKhi[NR * 512], g_QKlo[NR * 512];   // Q cols 0-255, K cols 256-511
__device__ __align__(256) float  g_L[(size_t)NR * NR];
__device__ __align__(256) __half g_Phi[(size_t)NR * NR];

// ---------------- PTX helpers ----------------
__device__ __forceinline__ uint32_t s2u(const void* p) {
    uint32_t a;
    asm("{ .reg .u64 t; cvta.to.shared.u64 t, %1; cvt.u32.u64 %0, t; }" : "=r"(a) : "l"(p));
    return a;
}
__device__ __forceinline__ void cpasync16(uint32_t dst, const void* src) {
    asm volatile("cp.async.cg.shared.global [%0], [%1], 16;" :: "r"(dst), "l"(src));
}
__device__ __forceinline__ void cp_commit() {
    asm volatile("cp.async.commit_group;" ::: "memory");
}
template <int N>
__device__ __forceinline__ void cp_wait() {
    asm volatile("cp.async.wait_group %0;" :: "n"(N) : "memory");
}
__device__ __forceinline__ void ldsm4(uint32_t* r, uint32_t a) {
    asm volatile("ldmatrix.sync.aligned.m8n8.x4.shared.b16 {%0,%1,%2,%3}, [%4];"
                 : "=r"(r[0]), "=r"(r[1]), "=r"(r[2]), "=r"(r[3]) : "r"(a));
}
__device__ __forceinline__ void mma16816(float* d, const uint32_t* a, const uint32_t* b) {
    asm volatile(
        "mma.sync.aligned.m16n8k16.row.col.f32.f16.f16.f32 "
        "{%0,%1,%2,%3}, {%4,%5,%6,%7}, {%8,%9}, {%0,%1,%2,%3};"
        : "+f"(d[0]), "+f"(d[1]), "+f"(d[2]), "+f"(d[3])
        : "r"(a[0]), "r"(a[1]), "r"(a[2]), "r"(a[3]), "r"(b[0]), "r"(b[1]));
}

// ---------------- prep: fp16 hi/lo splits ----------------
__global__ void __launch_bounds__(256) prep_params(const float* __restrict__ R,
                                                   const float* __restrict__ E) {
    int idx = blockIdx.x * 256 + threadIdx.x;   // 65536
    int k = idx >> 8, j = idx & 255;            // R[k][j]
    float r = R[idx] * 0.0625f;                 // fold 1/sqrt(d)=1/16 into rotation
    __half h = __float2half_rn(r);
    g_Whi[j * DD + k] = h;
    g_Wlo[j * DD + k] = __float2half_rn(r - __half2float(h));
    float e = E[idx];
    h = __float2half_rn(e);
    g_Whi[(256 + j) * DD + k] = h;
    g_Wlo[(256 + j) * DD + k] = __float2half_rn(e - __half2float(h));
}

__global__ void __launch_bounds__(256) prep_x(const float* __restrict__ X) {
    int idx = blockIdx.x * 256 + threadIdx.x;   // 2M
    int r = idx >> 8, c = idx & 255;
    float v = X[idx];
    __half h = __float2half_rn(v);
    g_Xhi[idx] = h;
    g_Xlo[idx] = __float2half_rn(v - __half2float(h));
    g_XThi[(size_t)c * NR + r] = h;
}

// =====================================================================
// Wide 3-product GEMM: C = A @ B^T, CTA tile 128x256, 512 threads.
// 16 warps as 4m x 4n, each 32x64. BK=64, 2-stage ring (96 KB/stage).
// Stage layout: Ahi(16K) | Alo(16K) | Bhi(32K) | Blo(32K).
// mode 0: split fp16 out (Chi/Clo). mode 1: fp32 out (Cf).
// =====================================================================
#define STG512 98304

__device__ __forceinline__ void load512(char* st,
    const __half* pAh, const __half* pAl, int lda,
    const __half* pBh, const __half* pBl, int ldb, int kc, int tid) {
    const uint32_t b0 = s2u(st);
    #pragma unroll
    for (int i = 0; i < 2; ++i) {             // A tiles: 128x64
        int id = tid + i * 512;
        int r = id >> 3, q = id & 7;
        uint32_t off = (uint32_t)(r * 128) + (uint32_t)((q ^ (r & 7)) << 4);
        const size_t g = (size_t)r * lda + kc + q * 8;
        cpasync16(b0 + off, pAh + g);
        cpasync16(b0 + 16384 + off, pAl + g);
    }
    #pragma unroll
    for (int i = 0; i < 4; ++i) {             // B tiles: 256x64
        int id = tid + i * 512;
        int r = id >> 3, q = id & 7;
        uint32_t off = (uint32_t)(r * 128) + (uint32_t)((q ^ (r & 7)) << 4);
        const size_t g = (size_t)r * ldb + kc + q * 8;
        cpasync16(b0 + 32768 + off, pBh + g);
        cpasync16(b0 + 65536 + off, pBl + g);
    }
}

__device__ __forceinline__ void compute512(char* st, float acc[2][8][4],
                                           int lane, int wm, int wn) {
    const uint32_t bA = s2u(st), bAl = bA + 16384, bB = bA + 32768, bBl = bA + 65536;
    #pragma unroll
    for (int k16 = 0; k16 < 4; ++k16) {
        uint32_t ah[2][4], al[2][4];
        #pragma unroll
        for (int mt = 0; mt < 2; ++mt) {
            int row = wm * 32 + mt * 16 + (lane & 15);
            int c = k16 * 2 + (lane >> 4);
            uint32_t off = (uint32_t)(row * 128) + (uint32_t)((c ^ (row & 7)) << 4);
            ldsm4(ah[mt], bA + off);
            ldsm4(al[mt], bAl + off);
        }
        #pragma unroll
        for (int p = 0; p < 4; ++p) {
            int n = wn * 64 + p * 16 + ((lane >> 4) << 3) + (lane & 7);
            int c = k16 * 2 + ((lane >> 3) & 1);
            uint32_t off = (uint32_t)(n * 128) + (uint32_t)((c ^ (n & 7)) << 4);
            uint32_t bh[4], bl[4];
            ldsm4(bh, bB + off);
            ldsm4(bl, bBl + off);
            #pragma unroll
            for (int mt = 0; mt < 2; ++mt) {
                mma16816(acc[mt][2 * p + 0], ah[mt], &bh[0]);
                mma16816(acc[mt][2 * p + 1], ah[mt], &bh[2]);
                mma16816(acc[mt][2 * p + 0], al[mt], &bh[0]);
                mma16816(acc[mt][2 * p + 1], al[mt], &bh[2]);
                mma16816(acc[mt][2 * p + 0], ah[mt], &bl[0]);
                mma16816(acc[mt][2 * p + 1], ah[mt], &bl[2]);
            }
        }
    }
}

__global__ void __launch_bounds__(512, 1) gemm512(
    const __half* __restrict__ Ahi, const __half* __restrict__ Alo, int lda,
    const __half* __restrict__ Bhi, const __half* __restrict__ Blo, int ldb,
    int K, int mode, float* __restrict__ Cf,
    __half* __restrict__ Chi, __half* __restrict__ Clo, int ldc) {
    extern __shared__ char sm[];
    const int tid = threadIdx.x, lane = tid & 31, wid = tid >> 5;
    const int wm = wid & 3, wn = wid >> 2;
    const int rowA = blockIdx.y * 128, colB = blockIdx.x * 256;

    const __half* pAh = Ahi + (size_t)rowA * lda;
    const __half* pAl = Alo + (size_t)rowA * lda;
    const __half* pBh = Bhi + (size_t)colB * ldb;
    const __half* pBl = Blo + (size_t)colB * ldb;

    float acc[2][8][4];
    #pragma unroll
    for (int a = 0; a < 2; ++a)
        #pragma unroll
        for (int b = 0; b < 8; ++b)
            #pragma unroll
            for (int c = 0; c < 4; ++c) acc[a][b][c] = 0.f;

    const int NC = K >> 6;
    load512(sm, pAh, pAl, lda, pBh, pBl, ldb, 0, tid);
    cp_commit();
    load512(sm + STG512, pAh, pAl, lda, pBh, pBl, ldb, 64, tid);
    cp_commit();

    for (int c = 0; c < NC; ++c) {
        cp_wait<1>();
        __syncthreads();
        compute512(sm + (c & 1) * STG512, acc, lane, wm, wn);
        __syncthreads();
        int nx = c + 2;
        if (nx < NC) load512(sm + (c & 1) * STG512, pAh, pAl, lda, pBh, pBl, ldb, nx * 64, tid);
        cp_commit();
    }

    const int quad = lane >> 2, tc = lane & 3;
    #pragma unroll
    for (int mt = 0; mt < 2; ++mt) {
        #pragma unroll
        for (int h = 0; h < 2; ++h) {
            const int row = rowA + wm * 32 + mt * 16 + quad + h * 8;
            #pragma unroll
            for (int nt = 0; nt < 8; ++nt) {
                const int col = colB + wn * 64 + nt * 8 + tc * 2;
                float v0 = acc[mt][nt][h * 2 + 0];
                float v1 = acc[mt][nt][h * 2 + 1];
                if (mode == 1) {
                    *(float2*)(Cf + (size_t)row * ldc + col) = make_float2(v0, v1);
                } else {
                    __half h0 = __float2half_rn(v0), h1 = __float2half_rn(v1);
                    __half l0 = __float2half_rn(v0 - __half2float(h0));
                    __half l1 = __float2half_rn(v1 - __half2float(h1));
                    *(__half2*)(Chi + (size_t)row * ldc + col) = __halves2half2(h0, h1);
                    *(__half2*)(Clo + (size_t)row * ldc + col) = __halves2half2(l0, l1);
                }
            }
        }
    }
}

// =====================================================================
// Single-product GEMM (O = P @ X^T): CTA 128x128, 256 thr, 3-stage, 2 CTA/SM
// =====================================================================
#define TILE_B 16384
#define NSTAGE 3

__device__ __forceinline__ void load_o(char* st, const __half* pA, const __half* pB,
                                       int K, int kc, int tid) {
    const uint32_t b0 = s2u(st);
    #pragma unroll
    for (int i = 0; i < 4; ++i) {
        int id = tid + i * 256;
        int r = id >> 3, q = id & 7;
        uint32_t off = (uint32_t)(r * 128) + (uint32_t)((q ^ (r & 7)) << 4);
        const size_t g = (size_t)r * K + kc + q * 8;
        cpasync16(b0 + off, pA + g);
        cpasync16(b0 + TILE_B + off, pB + g);
    }
}

__global__ void __launch_bounds__(256, 2) gemm_o(
    const __half* __restrict__ A, const __half* __restrict__ B,
    int K, float* __restrict__ Cf, int ldc) {
    extern __shared__ char sm[];
    const int tid = threadIdx.x, lane = tid & 31, wid = tid >> 5;
    const int wm = wid & 3, wn = wid >> 2;
    const int rowA = blockIdx.y * 128, colB = blockIdx.x * 128;
    const __half* pA = A + (size_t)rowA * K;
    const __half* pB = B + (size_t)colB * K;

    float acc[2][8][4];
    #pragma unroll
    for (int a = 0; a < 2; ++a)
        #pragma unroll
        for (int b = 0; b < 8; ++b)
            #pragma unroll
            for (int c = 0; c < 4; ++c) acc[a][b][c] = 0.f;

    const int NC = K >> 6;
    #pragma unroll
    for (int s = 0; s < NSTAGE; ++s) {
        if (s < NC) load_o(sm + s * 2 * TILE_B, pA, pB, K, s * 64, tid);
        cp_commit();
    }

    for (int c = 0; c < NC; ++c) {
        cp_wait<NSTAGE - 1>();
        __syncthreads();
        char* st = sm + (c % NSTAGE) * 2 * TILE_B;
        const uint32_t bA = s2u(st), bB = bA + TILE_B;
        #pragma unroll
        for (int k16 = 0; k16 < 4; ++k16) {
            uint32_t ah[2][4], bh[4][4];
            #pragma unroll
            for (int mt = 0; mt < 2; ++mt) {
                int row = wm * 32 + mt * 16 + (lane & 15);
                int cc = k16 * 2 + (lane >> 4);
                uint32_t off = (uint32_t)(row * 128) + (uint32_t)((cc ^ (row & 7)) << 4);
                ldsm4(ah[mt], bA + off);
            }
            #pragma unroll
            for (int p = 0; p < 4; ++p) {
                int n = wn * 64 + p * 16 + ((lane >> 4) << 3) + (lane & 7);
                int cc = k16 * 2 + ((lane >> 3) & 1);
                uint32_t off = (uint32_t)(n * 128) + (uint32_t)((cc ^ (n & 7)) << 4);
                ldsm4(bh[p], bB + off);
            }
            #pragma unroll
            for (int mt = 0; mt < 2; ++mt)
                #pragma unroll
                for (int p = 0; p < 4; ++p) {
                    mma16816(acc[mt][2 * p + 0], ah[mt], &bh[p][0]);
                    mma16816(acc[mt][2 * p + 1], ah[mt], &bh[p][2]);
                }
        }
        __syncthreads();
        int nx = c + NSTAGE;
        if (nx < NC) load_o(sm + (nx % NSTAGE) * 2 * TILE_B, pA, pB, K, nx * 64, tid);
        cp_commit();
    }

    const int quad = lane >> 2, tc = lane & 3;
    #pragma unroll
    for (int mt = 0; mt < 2; ++mt)
        #pragma unroll
        for (int h = 0; h < 2; ++h) {
            const int row = rowA + wm * 32 + mt * 16 + quad + h * 8;
            #pragma unroll
            for (int nt = 0; nt < 8; ++nt) {
                const int col = colB + wn * 64 + nt * 8 + tc * 2;
                *(float2*)(Cf + (size_t)row * ldc + col) =
                    make_float2(acc[mt][nt][h * 2 + 0], acc[mt][nt][h * 2 + 1]);
            }
        }
}

// ---------------- row softmax: Phi = fp16(softmax(L)), vectorized ----------------
__global__ void __launch_bounds__(256) softmax_k() {
    __shared__ float red[256];
    const int row = blockIdx.x;
    const int t = threadIdx.x;
    const float4* Lr = (const float4*)(g_L + (size_t)row * NR);
    float4 v[8];
    float m = -3.4e38f;
    #pragma unroll
    for (int i = 0; i < 8; ++i) {
        v[i] = Lr[t + i * 256];
        m = fmaxf(m, fmaxf(fmaxf(v[i].x, v[i].y), fmaxf(v[i].z, v[i].w)));
    }
    red[t] = m; __syncthreads();
    for (int s = 128; s > 0; s >>= 1) {
        if (t < s) red[t] = fmaxf(red[t], red[t + s]);
        __syncthreads();
    }
    m = red[0]; __syncthreads();
    float sum = 0.f;
    #pragma unroll
    for (int i = 0; i < 8; ++i) {
        v[i].x = __expf(v[i].x - m); v[i].y = __expf(v[i].y - m);
        v[i].z = __expf(v[i].z - m); v[i].w = __expf(v[i].w - m);
        sum += (v[i].x + v[i].y) + (v[i].z + v[i].w);
    }
    red[t] = sum; __syncthreads();
    for (int s = 128; s > 0; s >>= 1) {
        if (t < s) red[t] += red[t + s];
        __syncthreads();
    }
    const float inv = 1.0f / red[0];
    uint2* ph = (uint2*)(g_Phi + (size_t)row * NR);
    #pragma unroll
    for (int i = 0; i < 8; ++i) {
        __half2 a = __floats2half2_rn(v[i].x * inv, v[i].y * inv);
        __half2 b = __floats2half2_rn(v[i].z * inv, v[i].w * inv);
        uint2 w;
        w.x = *(uint32_t*)&a;
        w.y = *(uint32_t*)&b;
        ph[t + i * 256] = w;
    }
}

// ---------------- launch ----------------
extern "C" void kernel_launch(void* const* d_in, const int* in_sizes, int n_in,
                              void* d_out, int out_size) {
    const float* R = (const float*)d_in[0];
    const float* E = (const float*)d_in[1];
    const float* X = (const float*)d_in[2];
    float* out = (float*)d_out;

    const int SMEMW = 2 * STG512;            // 192 KB
    const int SMEMO = NSTAGE * 2 * TILE_B;   // 96 KB
    cudaFuncSetAttribute(gemm512, cudaFuncAttributeMaxDynamicSharedMemorySize, SMEMW);
    cudaFuncSetAttribute(gemm_o, cudaFuncAttributeMaxDynamicSharedMemorySize, SMEMO);

    void *xhi, *xlo, *xthi, *whi, *wlo, *qkhi, *qklo, *lptr, *phi;
    cudaGetSymbolAddress(&xhi, g_Xhi);   cudaGetSymbolAddress(&xlo, g_Xlo);
    cudaGetSymbolAddress(&xthi, g_XThi);
    cudaGetSymbolAddress(&whi, g_Whi);   cudaGetSymbolAddress(&wlo, g_Wlo);
    cudaGetSymbolAddress(&qkhi, g_QKhi); cudaGetSymbolAddress(&qklo, g_QKlo);
    cudaGetSymbolAddress(&lptr, g_L);
    cudaGetSymbolAddress(&phi, g_Phi);

    prep_params<<<DD * DD / 256, 256>>>(R, E);
    prep_x<<<NR, 256>>>(X);

    // QK = X @ [R/16 | E]  (split out, ldc=512)
    gemm512<<<dim3(2, 64), 512, SMEMW>>>((__half*)xhi, (__half*)xlo, DD,
                                         (__half*)whi, (__half*)wlo, DD,
                                         DD, 0, nullptr, (__half*)qkhi, (__half*)qklo, 512);
    // L = Q @ K^T  (fp32 out)
    gemm512<<<dim3(32, 64), 512, SMEMW>>>((__half*)qkhi, (__half*)qklo, 512,
                                          (__half*)qkhi + 256, (__half*)qklo + 256, 512,
                                          DD, 1, (float*)lptr, nullptr, nullptr, NR);
    // P = softmax(L)
    softmax_k<<<NR, 256>>>();
    // O = P @ X
    gemm_o<<<dim3(2, 64), 256, SMEMO>>>((__half*)phi, (__half*)xthi, NR, out, DD);
}

// round 7
// speedup vs baseline: 1.3878x; 1.0040x over previous
#include <cuda_runtime.h>
#include <cuda_fp16.h>
#include <cstdint>

#define NR 8192
#define DD 256

// ---------------- device scratch (allocation-free) ----------------
__device__ __align__(256) __half g_Xhi[NR * DD], g_Xlo[NR * DD];
__device__ __align__(256) __half g_XThi[DD * NR];
__device__ __align__(256) __half g_Whi[512 * DD], g_Wlo[512 * DD];     // [Rt/16 ; Et]
__device__ __align__(256) __half g_QKhi[NR * 512], g_QKlo[NR * 512];   // Q cols 0-255, K cols 256-511
__device__ __align__(256) float  g_L[(size_t)NR * NR];
__device__ __align__(256) __half g_Phi[(size_t)NR * NR];

// ---------------- PTX helpers ----------------
__device__ __forceinline__ uint32_t s2u(const void* p) {
    uint32_t a;
    asm("{ .reg .u64 t; cvta.to.shared.u64 t, %1; cvt.u32.u64 %0, t; }" : "=r"(a) : "l"(p));
    return a;
}
__device__ __forceinline__ void cpasync16(uint32_t dst, const void* src) {
    asm volatile("cp.async.cg.shared.global [%0], [%1], 16;" :: "r"(dst), "l"(src));
}
__device__ __forceinline__ void cp_commit() {
    asm volatile("cp.async.commit_group;" ::: "memory");
}
template <int N>
__device__ __forceinline__ void cp_wait() {
    asm volatile("cp.async.wait_group %0;" :: "n"(N) : "memory");
}
__device__ __forceinline__ void ldsm4(uint32_t* r, uint32_t a) {
    asm volatile("ldmatrix.sync.aligned.m8n8.x4.shared.b16 {%0,%1,%2,%3}, [%4];"
                 : "=r"(r[0]), "=r"(r[1]), "=r"(r[2]), "=r"(r[3]) : "r"(a));
}
__device__ __forceinline__ void mma16816(float* d, const uint32_t* a, const uint32_t* b) {
    asm volatile(
        "mma.sync.aligned.m16n8k16.row.col.f32.f16.f16.f32 "
        "{%0,%1,%2,%3}, {%4,%5,%6,%7}, {%8,%9}, {%0,%1,%2,%3};"
        : "+f"(d[0]), "+f"(d[1]), "+f"(d[2]), "+f"(d[3])
        : "r"(a[0]), "r"(a[1]), "r"(a[2]), "r"(a[3]), "r"(b[0]), "r"(b[1]));
}

// ---------------- prep: fp16 hi/lo splits ----------------
__global__ void __launch_bounds__(256) prep_params(const float* __restrict__ R,
                                                   const float* __restrict__ E) {
    int idx = blockIdx.x * 256 + threadIdx.x;   // 65536
    int k = idx >> 8, j = idx & 255;            // R[k][j]
    float r = R[idx] * 0.0625f;                 // fold 1/sqrt(d)=1/16 into rotation
    __half h = __float2half_rn(r);
    g_Whi[j * DD + k] = h;
    g_Wlo[j * DD + k] = __float2half_rn(r - __half2float(h));
    float e = E[idx];
    h = __float2half_rn(e);
    g_Whi[(256 + j) * DD + k] = h;
    g_Wlo[(256 + j) * DD + k] = __float2half_rn(e - __half2float(h));
}

__global__ void __launch_bounds__(256) prep_x(const float* __restrict__ X) {
    int idx = blockIdx.x * 256 + threadIdx.x;   // 2M
    int r = idx >> 8, c = idx & 255;
    float v = X[idx];
    __half h = __float2half_rn(v);
    g_Xhi[idx] = h;
    g_Xlo[idx] = __float2half_rn(v - __half2float(h));
    g_XThi[(size_t)c * NR + r] = h;
}

// =====================================================================
// Wide 3-product GEMM: C = A @ B^T, CTA tile 128x256, 512 threads.
// 16 warps as 4m x 4n, each 32x64. BK=64, 2-stage ring (96 KB/stage).
// Stage layout: Ahi(16K) | Alo(16K) | Bhi(32K) | Blo(32K).
// mode 0: split fp16 out (Chi/Clo). mode 1: fp32 out (Cf).
// =====================================================================
#define STG512 98304

__device__ __forceinline__ void load512(char* st,
    const __half* pAh, const __half* pAl, int lda,
    const __half* pBh, const __half* pBl, int ldb, int kc, int tid) {
    const uint32_t b0 = s2u(st);
    #pragma unroll
    for (int i = 0; i < 2; ++i) {             // A tiles: 128x64
        int id = tid + i * 512;
        int r = id >> 3, q = id & 7;
        uint32_t off = (uint32_t)(r * 128) + (uint32_t)((q ^ (r & 7)) << 4);
        const size_t g = (size_t)r * lda + kc + q * 8;
        cpasync16(b0 + off, pAh + g);
        cpasync16(b0 + 16384 + off, pAl + g);
    }
    #pragma unroll
    for (int i = 0; i < 4; ++i) {             // B tiles: 256x64
        int id = tid + i * 512;
        int r = id >> 3, q = id & 7;
        uint32_t off = (uint32_t)(r * 128) + (uint32_t)((q ^ (r & 7)) << 4);
        const size_t g = (size_t)r * ldb + kc + q * 8;
        cpasync16(b0 + 32768 + off, pBh + g);
        cpasync16(b0 + 65536 + off, pBl + g);
    }
}

__device__ __forceinline__ void compute512(char* st, float acc[2][8][4],
                                           int lane, int wm, int wn) {
    const uint32_t bA = s2u(st), bAl = bA + 16384, bB = bA + 32768, bBl = bA + 65536;
    #pragma unroll
    for (int k16 = 0; k16 < 4; ++k16) {
        uint32_t ah[2][4], al[2][4];
        #pragma unroll
        for (int mt = 0; mt < 2; ++mt) {
            int row = wm * 32 + mt * 16 + (lane & 15);
            int c = k16 * 2 + (lane >> 4);
            uint32_t off = (uint32_t)(row * 128) + (uint32_t)((c ^ (row & 7)) << 4);
            ldsm4(ah[mt], bA + off);
            ldsm4(al[mt], bAl + off);
        }
        #pragma unroll
        for (int p = 0; p < 4; ++p) {
            int n = wn * 64 + p * 16 + ((lane >> 4) << 3) + (lane & 7);
            int c = k16 * 2 + ((lane >> 3) & 1);
            uint32_t off = (uint32_t)(n * 128) + (uint32_t)((c ^ (n & 7)) << 4);
            uint32_t bh[4], bl[4];
            ldsm4(bh, bB + off);
            ldsm4(bl, bBl + off);
            #pragma unroll
            for (int mt = 0; mt < 2; ++mt) {
                mma16816(acc[mt][2 * p + 0], ah[mt], &bh[0]);
                mma16816(acc[mt][2 * p + 1], ah[mt], &bh[2]);
                mma16816(acc[mt][2 * p + 0], al[mt], &bh[0]);
                mma16816(acc[mt][2 * p + 1], al[mt], &bh[2]);
                mma16816(acc[mt][2 * p + 0], ah[mt], &bl[0]);
                mma16816(acc[mt][2 * p + 1], ah[mt], &bl[2]);
            }
        }
    }
}

__global__ void __launch_bounds__(512, 1) gemm512(
    const __half* __restrict__ Ahi, const __half* __restrict__ Alo, int lda,
    const __half* __restrict__ Bhi, const __half* __restrict__ Blo, int ldb,
    int K, int mode, float* __restrict__ Cf,
    __half* __restrict__ Chi, __half* __restrict__ Clo, int ldc) {
    extern __shared__ char sm[];
    const int tid = threadIdx.x, lane = tid & 31, wid = tid >> 5;
    const int wm = wid & 3, wn = wid >> 2;
    const int rowA = blockIdx.y * 128, colB = blockIdx.x * 256;

    const __half* pAh = Ahi + (size_t)rowA * lda;
    const __half* pAl = Alo + (size_t)rowA * lda;
    const __half* pBh = Bhi + (size_t)colB * ldb;
    const __half* pBl = Blo + (size_t)colB * ldb;

    float acc[2][8][4];
    #pragma unroll
    for (int a = 0; a < 2; ++a)
        #pragma unroll
        for (int b = 0; b < 8; ++b)
            #pragma unroll
            for (int c = 0; c < 4; ++c) acc[a][b][c] = 0.f;

    const int NC = K >> 6;
    load512(sm, pAh, pAl, lda, pBh, pBl, ldb, 0, tid);
    cp_commit();
    load512(sm + STG512, pAh, pAl, lda, pBh, pBl, ldb, 64, tid);
    cp_commit();

    for (int c = 0; c < NC; ++c) {
        cp_wait<1>();
        __syncthreads();
        compute512(sm + (c & 1) * STG512, acc, lane, wm, wn);
        __syncthreads();
        int nx = c + 2;
        if (nx < NC) load512(sm + (c & 1) * STG512, pAh, pAl, lda, pBh, pBl, ldb, nx * 64, tid);
        cp_commit();
    }

    const int quad = lane >> 2, tc = lane & 3;
    #pragma unroll
    for (int mt = 0; mt < 2; ++mt) {
        #pragma unroll
        for (int h = 0; h < 2; ++h) {
            const int row = rowA + wm * 32 + mt * 16 + quad + h * 8;
            #pragma unroll
            for (int nt = 0; nt < 8; ++nt) {
                const int col = colB + wn * 64 + nt * 8 + tc * 2;
                float v0 = acc[mt][nt][h * 2 + 0];
                float v1 = acc[mt][nt][h * 2 + 1];
                if (mode == 1) {
                    *(float2*)(Cf + (size_t)row * ldc + col) = make_float2(v0, v1);
                } else {
                    __half h0 = __float2half_rn(v0), h1 = __float2half_rn(v1);
                    __half l0 = __float2half_rn(v0 - __half2float(h0));
                    __half l1 = __float2half_rn(v1 - __half2float(h1));
                    *(__half2*)(Chi + (size_t)row * ldc + col) = __halves2half2(h0, h1);
                    *(__half2*)(Clo + (size_t)row * ldc + col) = __halves2half2(l0, l1);
                }
            }
        }
    }
}

// =====================================================================
// Single-product GEMM (O = P @ X^T): CTA 128x128, 256 thr, 3-stage, 2 CTA/SM
// =====================================================================
#define TILE_B 16384
#define NSTAGE 3

__device__ __forceinline__ void load_o(char* st, const __half* pA, const __half* pB,
                                       int K, int kc, int tid) {
    const uint32_t b0 = s2u(st);
    #pragma unroll
    for (int i = 0; i < 4; ++i) {
        int id = tid + i * 256;
        int r = id >> 3, q = id & 7;
        uint32_t off = (uint32_t)(r * 128) + (uint32_t)((q ^ (r & 7)) << 4);
        const size_t g = (size_t)r * K + kc + q * 8;
        cpasync16(b0 + off, pA + g);
        cpasync16(b0 + TILE_B + off, pB + g);
    }
}

__global__ void __launch_bounds__(256, 2) gemm_o(
    const __half* __restrict__ A, const __half* __restrict__ B,
    int K, float* __restrict__ Cf, int ldc) {
    extern __shared__ char sm[];
    const int tid = threadIdx.x, lane = tid & 31, wid = tid >> 5;
    const int wm = wid & 3, wn = wid >> 2;
    const int rowA = blockIdx.y * 128, colB = blockIdx.x * 128;
    const __half* pA = A + (size_t)rowA * K;
    const __half* pB = B + (size_t)colB * K;

    float acc[2][8][4];
    #pragma unroll
    for (int a = 0; a < 2; ++a)
        #pragma unroll
        for (int b = 0; b < 8; ++b)
            #pragma unroll
            for (int c = 0; c < 4; ++c) acc[a][b][c] = 0.f;

    const int NC = K >> 6;
    #pragma unroll
    for (int s = 0; s < NSTAGE; ++s) {
        if (s < NC) load_o(sm + s * 2 * TILE_B, pA, pB, K, s * 64, tid);
        cp_commit();
    }

    for (int c = 0; c < NC; ++c) {
        cp_wait<NSTAGE - 1>();
        __syncthreads();
        char* st = sm + (c % NSTAGE) * 2 * TILE_B;
        const uint32_t bA = s2u(st), bB = bA + TILE_B;
        #pragma unroll
        for (int k16 = 0; k16 < 4; ++k16) {
            uint32_t ah[2][4], bh[4][4];
            #pragma unroll
            for (int mt = 0; mt < 2; ++mt) {
                int row = wm * 32 + mt * 16 + (lane & 15);
                int cc = k16 * 2 + (lane >> 4);
                uint32_t off = (uint32_t)(row * 128) + (uint32_t)((cc ^ (row & 7)) << 4);
                ldsm4(ah[mt], bA + off);
            }
            #pragma unroll
            for (int p = 0; p < 4; ++p) {
                int n = wn * 64 + p * 16 + ((lane >> 4) << 3) + (lane & 7);
                int cc = k16 * 2 + ((lane >> 3) & 1);
                uint32_t off = (uint32_t)(n * 128) + (uint32_t)((cc ^ (n & 7)) << 4);
                ldsm4(bh[p], bB + off);
            }
            #pragma unroll
            for (int mt = 0; mt < 2; ++mt)
                #pragma unroll
                for (int p = 0; p < 4; ++p) {
                    mma16816(acc[mt][2 * p + 0], ah[mt], &bh[p][0]);
                    mma16816(acc[mt][2 * p + 1], ah[mt], &bh[p][2]);
                }
        }
        __syncthreads();
        int nx = c + NSTAGE;
        if (nx < NC) load_o(sm + (nx % NSTAGE) * 2 * TILE_B, pA, pB, K, nx * 64, tid);
        cp_commit();
    }

    const int quad = lane >> 2, tc = lane & 3;
    #pragma unroll
    for (int mt = 0; mt < 2; ++mt)
        #pragma unroll
        for (int h = 0; h < 2; ++h) {
            const int row = rowA + wm * 32 + mt * 16 + quad + h * 8;
            #pragma unroll
            for (int nt = 0; nt < 8; ++nt) {
                const int col = colB + wn * 64 + nt * 8 + tc * 2;
                *(float2*)(Cf + (size_t)row * ldc + col) =
                    make_float2(acc[mt][nt][h * 2 + 0], acc[mt][nt][h * 2 + 1]);
            }
        }
}

// ---------------- row softmax: Phi = fp16(softmax(L)), vectorized ----------------
__global__ void __launch_bounds__(256) softmax_k() {
    __shared__ float red[256];
    const int row = blockIdx.x;
    const int t = threadIdx.x;
    const float4* Lr = (const float4*)(g_L + (size_t)row * NR);
    float4 v[8];
    float m = -3.4e38f;
    #pragma unroll
    for (int i = 0; i < 8; ++i) {
        v[i] = Lr[t + i * 256];
        m = fmaxf(m, fmaxf(fmaxf(v[i].x, v[i].y), fmaxf(v[i].z, v[i].w)));
    }
    red[t] = m; __syncthreads();
    for (int s = 128; s > 0; s >>= 1) {
        if (t < s) red[t] = fmaxf(red[t], red[t + s]);
        __syncthreads();
    }
    m = red[0]; __syncthreads();
    float sum = 0.f;
    #pragma unroll
    for (int i = 0; i < 8; ++i) {
        v[i].x = __expf(v[i].x - m); v[i].y = __expf(v[i].y - m);
        v[i].z = __expf(v[i].z - m); v[i].w = __expf(v[i].w - m);
        sum += (v[i].x + v[i].y) + (v[i].z + v[i].w);
    }
    red[t] = sum; __syncthreads();
    for (int s = 128; s > 0; s >>= 1) {
        if (t < s) red[t] += red[t + s];
        __syncthreads();
    }
    const float inv = 1.0f / red[0];
    uint2* ph = (uint2*)(g_Phi + (size_t)row * NR);
    #pragma unroll
    for (int i = 0; i < 8; ++i) {
        __half2 a = __floats2half2_rn(v[i].x * inv, v[i].y * inv);
        __half2 b = __floats2half2_rn(v[i].z * inv, v[i].w * inv);
        uint2 w;
        w.x = *(uint32_t*)&a;
        w.y = *(uint32_t*)&b;
        ph[t + i * 256] = w;
    }
}

// ---------------- launch ----------------
extern "C" void kernel_launch(void* const* d_in, const int* in_sizes, int n_in,
                              void* d_out, int out_size) {
    const float* R = (const float*)d_in[0];
    const float* E = (const float*)d_in[1];
    const float* X = (const float*)d_in[2];
    float* out = (float*)d_out;

    const int SMEMW = 2 * STG512;            // 192 KB
    const int SMEMO = NSTAGE * 2 * TILE_B;   // 96 KB
    cudaFuncSetAttribute(gemm512, cudaFuncAttributeMaxDynamicSharedMemorySize, SMEMW);
    cudaFuncSetAttribute(gemm_o, cudaFuncAttributeMaxDynamicSharedMemorySize, SMEMO);

    void *xhi, *xlo, *xthi, *whi, *wlo, *qkhi, *qklo, *lptr, *phi;
    cudaGetSymbolAddress(&xhi, g_Xhi);   cudaGetSymbolAddress(&xlo, g_Xlo);
    cudaGetSymbolAddress(&xthi, g_XThi);
    cudaGetSymbolAddress(&whi, g_Whi);   cudaGetSymbolAddress(&wlo, g_Wlo);
    cudaGetSymbolAddress(&qkhi, g_QKhi); cudaGetSymbolAddress(&qklo, g_QKlo);
    cudaGetSymbolAddress(&lptr, g_L);
    cudaGetSymbolAddress(&phi, g_Phi);

    prep_params<<<DD * DD / 256, 256>>>(R, E);
    prep_x<<<NR, 256>>>(X);

    // QK = X @ [R/16 | E]  (split out, ldc=512)
    gemm512<<<dim3(2, 64), 512, SMEMW>>>((__half*)xhi, (__half*)xlo, DD,
                                         (__half*)whi, (__half*)wlo, DD,
                                         DD, 0, nullptr, (__half*)qkhi, (__half*)qklo, 512);
    // L = Q @ K^T  (fp32 out)
    gemm512<<<dim3(32, 64), 512, SMEMW>>>((__half*)qkhi, (__half*)qklo, 512,
                                          (__half*)qkhi + 256, (__half*)qklo + 256, 512,
                                          DD, 1, (float*)lptr, nullptr, nullptr, NR);
    // P = softmax(L)
    softmax_k<<<NR, 256>>>();
    // O = P @ X
    gemm_o<<<dim3(2, 64), 256, SMEMO>>>((__half*)phi, (__half*)xthi, NR, out, DD);
}

// round 8
// speedup vs baseline: 1.4279x; 1.0289x over previous
#include <cuda_runtime.h>
#include <cuda_fp16.h>
#include <cstdint>

#define NR 8192
#define DD 256

// ---------------- device scratch (allocation-free) ----------------
__device__ __align__(256) __half g_Xhi[NR * DD], g_Xlo[NR * DD];
__device__ __align__(256) __half g_XThi[DD * NR];
__device__ __align__(256) __half g_Whi[512 * DD], g_Wlo[512 * DD];     // [Rt/16 ; Et]
__device__ __align__(256) __half g_QKhi[NR * 512], g_QKlo[NR * 512];   // Q cols 0-255, K cols 256-511
__device__ __align__(256) float  g_L[(size_t)NR * NR];
__device__ __align__(256) __half g_Phi[(size_t)NR * NR];

// ---------------- PTX helpers ----------------
__device__ __forceinline__ uint32_t s2u(const void* p) {
    uint32_t a;
    asm("{ .reg .u64 t; cvta.to.shared.u64 t, %1; cvt.u32.u64 %0, t; }" : "=r"(a) : "l"(p));
    return a;
}
__device__ __forceinline__ void cpasync16(uint32_t dst, const void* src) {
    asm volatile("cp.async.cg.shared.global [%0], [%1], 16;" :: "r"(dst), "l"(src));
}
__device__ __forceinline__ void cp_commit() {
    asm volatile("cp.async.commit_group;" ::: "memory");
}
template <int N>
__device__ __forceinline__ void cp_wait() {
    asm volatile("cp.async.wait_group %0;" :: "n"(N) : "memory");
}
__device__ __forceinline__ void ldsm4(uint32_t* r, uint32_t a) {
    asm volatile("ldmatrix.sync.aligned.m8n8.x4.shared.b16 {%0,%1,%2,%3}, [%4];"
                 : "=r"(r[0]), "=r"(r[1]), "=r"(r[2]), "=r"(r[3]) : "r"(a));
}
__device__ __forceinline__ void mma16816(float* d, const uint32_t* a, const uint32_t* b) {
    asm volatile(
        "mma.sync.aligned.m16n8k16.row.col.f32.f16.f16.f32 "
        "{%0,%1,%2,%3}, {%4,%5,%6,%7}, {%8,%9}, {%0,%1,%2,%3};"
        : "+f"(d[0]), "+f"(d[1]), "+f"(d[2]), "+f"(d[3])
        : "r"(a[0]), "r"(a[1]), "r"(a[2]), "r"(a[3]), "r"(b[0]), "r"(b[1]));
}

// ---------------- prep: fp16 hi/lo splits ----------------
__global__ void __launch_bounds__(256) prep_params(const float* __restrict__ R,
                                                   const float* __restrict__ E) {
    int idx = blockIdx.x * 256 + threadIdx.x;   // 65536
    int k = idx >> 8, j = idx & 255;            // R[k][j]
    float r = R[idx] * 0.0625f;                 // fold 1/sqrt(d)=1/16 into rotation
    __half h = __float2half_rn(r);
    g_Whi[j * DD + k] = h;
    g_Wlo[j * DD + k] = __float2half_rn(r - __half2float(h));
    float e = E[idx];
    h = __float2half_rn(e);
    g_Whi[(256 + j) * DD + k] = h;
    g_Wlo[(256 + j) * DD + k] = __float2half_rn(e - __half2float(h));
}

__global__ void __launch_bounds__(256) prep_x(const float* __restrict__ X) {
    int idx = blockIdx.x * 256 + threadIdx.x;   // 2M
    int r = idx >> 8, c = idx & 255;
    float v = X[idx];
    __half h = __float2half_rn(v);
    g_Xhi[idx] = h;
    g_Xlo[idx] = __float2half_rn(v - __half2float(h));
    g_XThi[(size_t)c * NR + r] = h;
}

// =====================================================================
// Persistent wide 3-product GEMM: C = A @ B^T, tile 128x256, 512 thr.
// 16 warps as 4m x 4n, each 32x64. BK=64, continuous 2-stage ring that
// streams across tile boundaries (pipeline never drains).
// mode 0: split fp16 out (Chi/Clo). mode 1: fp32 out (Cf).
// =====================================================================
#define STG512 98304

__device__ __forceinline__ void load512(char* st,
    const __half* pAh, const __half* pAl, int lda,
    const __half* pBh, const __half* pBl, int ldb, int kc, int tid) {
    const uint32_t b0 = s2u(st);
    #pragma unroll
    for (int i = 0; i < 2; ++i) {             // A tiles: 128x64
        int id = tid + i * 512;
        int r = id >> 3, q = id & 7;
        uint32_t off = (uint32_t)(r * 128) + (uint32_t)((q ^ (r & 7)) << 4);
        const size_t g = (size_t)r * lda + kc + q * 8;
        cpasync16(b0 + off, pAh + g);
        cpasync16(b0 + 16384 + off, pAl + g);
    }
    #pragma unroll
    for (int i = 0; i < 4; ++i) {             // B tiles: 256x64
        int id = tid + i * 512;
        int r = id >> 3, q = id & 7;
        uint32_t off = (uint32_t)(r * 128) + (uint32_t)((q ^ (r & 7)) << 4);
        const size_t g = (size_t)r * ldb + kc + q * 8;
        cpasync16(b0 + 32768 + off, pBh + g);
        cpasync16(b0 + 65536 + off, pBl + g);
    }
}

__device__ __forceinline__ void compute512(char* st, float acc[2][8][4],
                                           int lane, int wm, int wn) {
    const uint32_t bA = s2u(st), bAl = bA + 16384, bB = bA + 32768, bBl = bA + 65536;
    #pragma unroll
    for (int k16 = 0; k16 < 4; ++k16) {
        uint32_t ah[2][4], al[2][4];
        #pragma unroll
        for (int mt = 0; mt < 2; ++mt) {
            int row = wm * 32 + mt * 16 + (lane & 15);
            int c = k16 * 2 + (lane >> 4);
            uint32_t off = (uint32_t)(row * 128) + (uint32_t)((c ^ (row & 7)) << 4);
            ldsm4(ah[mt], bA + off);
            ldsm4(al[mt], bAl + off);
        }
        #pragma unroll
        for (int p = 0; p < 4; ++p) {
            int n = wn * 64 + p * 16 + ((lane >> 4) << 3) + (lane & 7);
            int c = k16 * 2 + ((lane >> 3) & 1);
            uint32_t off = (uint32_t)(n * 128) + (uint32_t)((c ^ (n & 7)) << 4);
            uint32_t bh[4], bl[4];
            ldsm4(bh, bB + off);
            ldsm4(bl, bBl + off);
            #pragma unroll
            for (int mt = 0; mt < 2; ++mt) {
                mma16816(acc[mt][2 * p + 0], ah[mt], &bh[0]);
                mma16816(acc[mt][2 * p + 1], ah[mt], &bh[2]);
                mma16816(acc[mt][2 * p + 0], al[mt], &bh[0]);
                mma16816(acc[mt][2 * p + 1], al[mt], &bh[2]);
                mma16816(acc[mt][2 * p + 0], ah[mt], &bl[0]);
                mma16816(acc[mt][2 * p + 1], ah[mt], &bl[2]);
            }
        }
    }
}

__device__ __forceinline__ void tile_ptrs512(int t, int bxm, int bxs,
    const __half* Ahi, const __half* Alo, const __half* Bhi, const __half* Blo,
    int lda, int ldb,
    const __half*& pAh, const __half*& pAl, const __half*& pBh, const __half*& pBl) {
    int by = t >> bxs, bx = t & bxm;
    pAh = Ahi + (size_t)(by * 128) * lda;
    pAl = Alo + (size_t)(by * 128) * lda;
    pBh = Bhi + (size_t)(bx * 256) * ldb;
    pBl = Blo + (size_t)(bx * 256) * ldb;
}

__global__ void __launch_bounds__(512, 1) gemm512p(
    const __half* __restrict__ Ahi, const __half* __restrict__ Alo, int lda,
    const __half* __restrict__ Bhi, const __half* __restrict__ Blo, int ldb,
    int K, int NT, int bxm, int bxs, int mode, float* __restrict__ Cf,
    __half* __restrict__ Chi, __half* __restrict__ Clo, int ldc) {
    extern __shared__ char sm[];
    const int tid = threadIdx.x, lane = tid & 31, wid = tid >> 5;
    const int wm = wid & 3, wn = wid >> 2;
    const int NC = K >> 6;

    // load cursor
    int lt = blockIdx.x, lc = 0, ldbuf = 0;
    const __half *lAh, *lAl, *lBh, *lBl;
    tile_ptrs512(lt, bxm, bxs, Ahi, Alo, Bhi, Blo, lda, ldb, lAh, lAl, lBh, lBl);

    // prologue: 2 chunks
    #pragma unroll
    for (int i = 0; i < 2; ++i) {
        if (lt < NT) {
            load512(sm + ldbuf * STG512, lAh, lAl, lda, lBh, lBl, ldb, lc * 64, tid);
            ldbuf ^= 1;
            if (++lc == NC) {
                lc = 0; lt += gridDim.x;
                if (lt < NT) tile_ptrs512(lt, bxm, bxs, Ahi, Alo, Bhi, Blo, lda, ldb, lAh, lAl, lBh, lBl);
            }
        }
        cp_commit();
    }

    int cbuf = 0;
    for (int t = blockIdx.x; t < NT; t += gridDim.x) {
        float acc[2][8][4];
        #pragma unroll
        for (int a = 0; a < 2; ++a)
            #pragma unroll
            for (int b = 0; b < 8; ++b)
                #pragma unroll
                for (int c = 0; c < 4; ++c) acc[a][b][c] = 0.f;

        for (int c = 0; c < NC; ++c) {
            cp_wait<1>();
            __syncthreads();
            compute512(sm + cbuf * STG512, acc, lane, wm, wn);
            cbuf ^= 1;
            __syncthreads();
            if (lt < NT) {
                load512(sm + ldbuf * STG512, lAh, lAl, lda, lBh, lBl, ldb, lc * 64, tid);
                ldbuf ^= 1;
                if (++lc == NC) {
                    lc = 0; lt += gridDim.x;
                    if (lt < NT) tile_ptrs512(lt, bxm, bxs, Ahi, Alo, Bhi, Blo, lda, ldb, lAh, lAl, lBh, lBl);
                }
            }
            cp_commit();
        }

        // epilogue for tile t (overlaps with in-flight loads of next tile)
        const int rowT = (t >> bxs) * 128, colT = (t & bxm) * 256;
        const int quad = lane >> 2, tc = lane & 3;
        #pragma unroll
        for (int mt = 0; mt < 2; ++mt) {
            #pragma unroll
            for (int h = 0; h < 2; ++h) {
                const int row = rowT + wm * 32 + mt * 16 + quad + h * 8;
                #pragma unroll
                for (int nt = 0; nt < 8; ++nt) {
                    const int col = colT + wn * 64 + nt * 8 + tc * 2;
                    float v0 = acc[mt][nt][h * 2 + 0];
                    float v1 = acc[mt][nt][h * 2 + 1];
                    if (mode == 1) {
                        *(float2*)(Cf + (size_t)row * ldc + col) = make_float2(v0, v1);
                    } else {
                        __half h0 = __float2half_rn(v0), h1 = __float2half_rn(v1);
                        __half l0 = __float2half_rn(v0 - __half2float(h0));
                        __half l1 = __float2half_rn(v1 - __half2float(h1));
                        *(__half2*)(Chi + (size_t)row * ldc + col) = __halves2half2(h0, h1);
                        *(__half2*)(Clo + (size_t)row * ldc + col) = __halves2half2(l0, l1);
                    }
                }
            }
        }
    }
}

// =====================================================================
// O = P @ X^T: tile 128x64, 256 thr (8 warps 4m x 2n, each 32x32),
// BK=64, 4-stage ring, 2 CTAs/SM, grid = 256 CTAs.
// =====================================================================
#define OSTG 24576
#define ONST 4

__device__ __forceinline__ void load_o(char* st, const __half* pA, const __half* pB,
                                       int K, int kc, int tid) {
    const uint32_t b0 = s2u(st);
    #pragma unroll
    for (int i = 0; i < 4; ++i) {             // A: 128x64
        int id = tid + i * 256;
        int r = id >> 3, q = id & 7;
        uint32_t off = (uint32_t)(r * 128) + (uint32_t)((q ^ (r & 7)) << 4);
        cpasync16(b0 + off, pA + (size_t)r * K + kc + q * 8);
    }
    #pragma unroll
    for (int i = 0; i < 2; ++i) {             // B: 64x64
        int id = tid + i * 256;
        int r = id >> 3, q = id & 7;
        uint32_t off = (uint32_t)(r * 128) + (uint32_t)((q ^ (r & 7)) << 4);
        cpasync16(b0 + 16384 + off, pB + (size_t)r * K + kc + q * 8);
    }
}

__global__ void __launch_bounds__(256, 2) gemm_o(
    const __half* __restrict__ A, const __half* __restrict__ B,
    int K, float* __restrict__ Cf, int ldc) {
    extern __shared__ char sm[];
    const int tid = threadIdx.x, lane = tid & 31, wid = tid >> 5;
    const int wm = wid & 3, wn = wid >> 2;
    const int rowA = blockIdx.y * 128, colB = blockIdx.x * 64;
    const __half* pA = A + (size_t)rowA * K;
    const __half* pB = B + (size_t)colB * K;

    float acc[2][4][4];
    #pragma unroll
    for (int a = 0; a < 2; ++a)
        #pragma unroll
        for (int b = 0; b < 4; ++b)
            #pragma unroll
            for (int c = 0; c < 4; ++c) acc[a][b][c] = 0.f;

    const int NC = K >> 6;
    #pragma unroll
    for (int s = 0; s < ONST; ++s) {
        if (s < NC) load_o(sm + s * OSTG, pA, pB, K, s * 64, tid);
        cp_commit();
    }

    for (int c = 0; c < NC; ++c) {
        cp_wait<ONST - 1>();
        __syncthreads();
        char* st = sm + (c % ONST) * OSTG;
        const uint32_t bA = s2u(st), bB = bA + 16384;
        #pragma unroll
        for (int k16 = 0; k16 < 4; ++k16) {
            uint32_t ah[2][4];
            #pragma unroll
            for (int mt = 0; mt < 2; ++mt) {
                int row = wm * 32 + mt * 16 + (lane & 15);
                int cc = k16 * 2 + (lane >> 4);
                uint32_t off = (uint32_t)(row * 128) + (uint32_t)((cc ^ (row & 7)) << 4);
                ldsm4(ah[mt], bA + off);
            }
            #pragma unroll
            for (int p = 0; p < 2; ++p) {
                int n = wn * 32 + p * 16 + ((lane >> 4) << 3) + (lane & 7);
                int cc = k16 * 2 + ((lane >> 3) & 1);
                uint32_t off = (uint32_t)(n * 128) + (uint32_t)((cc ^ (n & 7)) << 4);
                uint32_t bh[4];
                ldsm4(bh, bB + off);
                #pragma unroll
                for (int mt = 0; mt < 2; ++mt) {
                    mma16816(acc[mt][2 * p + 0], ah[mt], &bh[0]);
                    mma16816(acc[mt][2 * p + 1], ah[mt], &bh[2]);
                }
            }
        }
        __syncthreads();
        int nx = c + ONST;
        if (nx < NC) load_o(sm + (nx % ONST) * OSTG, pA, pB, K, nx * 64, tid);
        cp_commit();
    }

    const int quad = lane >> 2, tc = lane & 3;
    #pragma unroll
    for (int mt = 0; mt < 2; ++mt)
        #pragma unroll
        for (int h = 0; h < 2; ++h) {
            const int row = rowA + wm * 32 + mt * 16 + quad + h * 8;
            #pragma unroll
            for (int nt = 0; nt < 4; ++nt) {
                const int col = colB + wn * 32 + nt * 8 + tc * 2;
                *(float2*)(Cf + (size_t)row * ldc + col) =
                    make_float2(acc[mt][nt][h * 2 + 0], acc[mt][nt][h * 2 + 1]);
            }
        }
}

// ---------------- row softmax: Phi = fp16(softmax(L)), vectorized ----------------
__global__ void __launch_bounds__(256) softmax_k() {
    __shared__ float red[256];
    const int row = blockIdx.x;
    const int t = threadIdx.x;
    const float4* Lr = (const float4*)(g_L + (size_t)row * NR);
    float4 v[8];
    float m = -3.4e38f;
    #pragma unroll
    for (int i = 0; i < 8; ++i) {
        v[i] = Lr[t + i * 256];
        m = fmaxf(m, fmaxf(fmaxf(v[i].x, v[i].y), fmaxf(v[i].z, v[i].w)));
    }
    red[t] = m; __syncthreads();
    for (int s = 128; s > 0; s >>= 1) {
        if (t < s) red[t] = fmaxf(red[t], red[t + s]);
        __syncthreads();
    }
    m = red[0]; __syncthreads();
    float sum = 0.f;
    #pragma unroll
    for (int i = 0; i < 8; ++i) {
        v[i].x = __expf(v[i].x - m); v[i].y = __expf(v[i].y - m);
        v[i].z = __expf(v[i].z - m); v[i].w = __expf(v[i].w - m);
        sum += (v[i].x + v[i].y) + (v[i].z + v[i].w);
    }
    red[t] = sum; __syncthreads();
    for (int s = 128; s > 0; s >>= 1) {
        if (t < s) red[t] += red[t + s];
        __syncthreads();
    }
    const float inv = 1.0f / red[0];
    uint2* ph = (uint2*)(g_Phi + (size_t)row * NR);
    #pragma unroll
    for (int i = 0; i < 8; ++i) {
        __half2 a = __floats2half2_rn(v[i].x * inv, v[i].y * inv);
        __half2 b = __floats2half2_rn(v[i].z * inv, v[i].w * inv);
        uint2 w;
        w.x = *(uint32_t*)&a;
        w.y = *(uint32_t*)&b;
        ph[t + i * 256] = w;
    }
}

// ---------------- launch ----------------
extern "C" void kernel_launch(void* const* d_in, const int* in_sizes, int n_in,
                              void* d_out, int out_size) {
    const float* R = (const float*)d_in[0];
    const float* E = (const float*)d_in[1];
    const float* X = (const float*)d_in[2];
    float* out = (float*)d_out;

    const int SMEMW = 2 * STG512;        // 192 KB
    const int SMEMO = ONST * OSTG;       // 96 KB
    cudaFuncSetAttribute(gemm512p, cudaFuncAttributeMaxDynamicSharedMemorySize, SMEMW);
    cudaFuncSetAttribute(gemm_o, cudaFuncAttributeMaxDynamicSharedMemorySize, SMEMO);

    void *xhi, *xlo, *xthi, *whi, *wlo, *qkhi, *qklo, *lptr, *phi;
    cudaGetSymbolAddress(&xhi, g_Xhi);   cudaGetSymbolAddress(&xlo, g_Xlo);
    cudaGetSymbolAddress(&xthi, g_XThi);
    cudaGetSymbolAddress(&whi, g_Whi);   cudaGetSymbolAddress(&wlo, g_Wlo);
    cudaGetSymbolAddress(&qkhi, g_QKhi); cudaGetSymbolAddress(&qklo, g_QKlo);
    cudaGetSymbolAddress(&lptr, g_L);
    cudaGetSymbolAddress(&phi, g_Phi);

    prep_params<<<DD * DD / 256, 256>>>(R, E);
    prep_x<<<NR, 256>>>(X);

    // QK = X @ [R/16 | E]  (split out, ldc=512); 128 tiles (2 x 64)
    gemm512p<<<128, 512, SMEMW>>>((__half*)xhi, (__half*)xlo, DD,
                                  (__half*)whi, (__half*)wlo, DD,
                                  DD, 128, 1, 1, 0, nullptr,
                                  (__half*)qkhi, (__half*)qklo, 512);
    // L = Q @ K^T  (fp32 out); 2048 tiles (32 x 64), persistent 148 CTAs
    gemm512p<<<148, 512, SMEMW>>>((__half*)qkhi, (__half*)qklo, 512,
                                  (__half*)qkhi + 256, (__half*)qklo + 256, 512,
                                  DD, 2048, 31, 5, 1, (float*)lptr,
                                  nullptr, nullptr, NR);
    // P = softmax(L)
    softmax_k<<<NR, 256>>>();
    // O = P @ X  (256 CTAs, 2/SM)
    gemm_o<<<dim3(4, 64), 256, SMEMO>>>((__half*)phi, (__half*)xthi, NR, out, DD);
}

// round 9
// speedup vs baseline: 1.4568x; 1.0202x over previous
#include <cuda_runtime.h>
#include <cuda_fp16.h>
#include <cstdint>

#define NR 8192
#define DD 256

// ---------------- device scratch (allocation-free) ----------------
__device__ __align__(256) __half g_Xhi[NR * DD], g_Xlo[NR * DD];
__device__ __align__(256) __half g_XThi[DD * NR];
__device__ __align__(256) __half g_Whi[512 * DD], g_Wlo[512 * DD];     // [Rt/16 ; Et]
__device__ __align__(256) __half g_QKhi[NR * 512], g_QKlo[NR * 512];   // Q cols 0-255, K cols 256-511
__device__ __align__(256) float  g_L[(size_t)NR * NR];
__device__ __align__(256) __half g_Phi[(size_t)NR * NR];

// ---------------- PTX helpers ----------------
__device__ __forceinline__ uint32_t s2u(const void* p) {
    uint32_t a;
    asm("{ .reg .u64 t; cvta.to.shared.u64 t, %1; cvt.u32.u64 %0, t; }" : "=r"(a) : "l"(p));
    return a;
}
__device__ __forceinline__ void cpasync16(uint32_t dst, const void* src) {
    asm volatile("cp.async.cg.shared.global [%0], [%1], 16;" :: "r"(dst), "l"(src));
}
__device__ __forceinline__ void cp_commit() {
    asm volatile("cp.async.commit_group;" ::: "memory");
}
template <int N>
__device__ __forceinline__ void cp_wait() {
    asm volatile("cp.async.wait_group %0;" :: "n"(N) : "memory");
}
__device__ __forceinline__ void ldsm4(uint32_t* r, uint32_t a) {
    asm volatile("ldmatrix.sync.aligned.m8n8.x4.shared.b16 {%0,%1,%2,%3}, [%4];"
                 : "=r"(r[0]), "=r"(r[1]), "=r"(r[2]), "=r"(r[3]) : "r"(a));
}
__device__ __forceinline__ void mma16816(float* d, const uint32_t* a, const uint32_t* b) {
    asm volatile(
        "mma.sync.aligned.m16n8k16.row.col.f32.f16.f16.f32 "
        "{%0,%1,%2,%3}, {%4,%5,%6,%7}, {%8,%9}, {%0,%1,%2,%3};"
        : "+f"(d[0]), "+f"(d[1]), "+f"(d[2]), "+f"(d[3])
        : "r"(a[0]), "r"(a[1]), "r"(a[2]), "r"(a[3]), "r"(b[0]), "r"(b[1]));
}

// ---------------- prep: fp16 hi/lo splits ----------------
__global__ void __launch_bounds__(256) prep_params(const float* __restrict__ R,
                                                   const float* __restrict__ E) {
    int idx = blockIdx.x * 256 + threadIdx.x;   // 65536
    int k = idx >> 8, j = idx & 255;            // R[k][j]
    float r = R[idx] * 0.0625f;                 // fold 1/sqrt(d)=1/16 into rotation
    __half h = __float2half_rn(r);
    g_Whi[j * DD + k] = h;
    g_Wlo[j * DD + k] = __float2half_rn(r - __half2float(h));
    float e = E[idx];
    h = __float2half_rn(e);
    g_Whi[(256 + j) * DD + k] = h;
    g_Wlo[(256 + j) * DD + k] = __float2half_rn(e - __half2float(h));
}

__global__ void __launch_bounds__(256) prep_x(const float* __restrict__ X) {
    int idx = blockIdx.x * 256 + threadIdx.x;   // 2M
    int r = idx >> 8, c = idx & 255;
    float v = X[idx];
    __half h = __float2half_rn(v);
    g_Xhi[idx] = h;
    g_Xlo[idx] = __float2half_rn(v - __half2float(h));
    g_XThi[(size_t)c * NR + r] = h;
}

// =====================================================================
// Persistent wide 3-product GEMM: C = A @ B^T, CTA tile 128x256,
// 256 threads = 8 warps as 2m x 4n, each warp 64x64 (high intensity:
// 24 MAC/smem-byte vs 16 before). BK=64, continuous 2-stage ring.
// Stage layout: Ahi(16K) | Alo(16K) | Bhi(32K) | Blo(32K) = 96KB.
// mode 0: split fp16 out (Chi/Clo). mode 1: fp32 out (Cf).
// =====================================================================
#define STG512 98304

__device__ __forceinline__ void load512(char* st,
    const __half* pAh, const __half* pAl, int lda,
    const __half* pBh, const __half* pBl, int ldb, int kc, int tid) {
    const uint32_t b0 = s2u(st);
    #pragma unroll
    for (int i = 0; i < 4; ++i) {             // A tiles: 128x64 (1024 vec16)
        int id = tid + i * 256;
        int r = id >> 3, q = id & 7;
        uint32_t off = (uint32_t)(r * 128) + (uint32_t)((q ^ (r & 7)) << 4);
        const size_t g = (size_t)r * lda + kc + q * 8;
        cpasync16(b0 + off, pAh + g);
        cpasync16(b0 + 16384 + off, pAl + g);
    }
    #pragma unroll
    for (int i = 0; i < 8; ++i) {             // B tiles: 256x64 (2048 vec16)
        int id = tid + i * 256;
        int r = id >> 3, q = id & 7;
        uint32_t off = (uint32_t)(r * 128) + (uint32_t)((q ^ (r & 7)) << 4);
        const size_t g = (size_t)r * ldb + kc + q * 8;
        cpasync16(b0 + 32768 + off, pBh + g);
        cpasync16(b0 + 65536 + off, pBl + g);
    }
}

__device__ __forceinline__ void compute512(char* st, float acc[4][8][4],
                                           int lane, int wm, int wn) {
    const uint32_t bA = s2u(st), bAl = bA + 16384, bB = bA + 32768, bBl = bA + 65536;
    #pragma unroll
    for (int k16 = 0; k16 < 4; ++k16) {
        uint32_t ah[4][4], al[4][4];
        #pragma unroll
        for (int mt = 0; mt < 4; ++mt) {
            int row = wm * 64 + mt * 16 + (lane & 15);
            int c = k16 * 2 + (lane >> 4);
            uint32_t off = (uint32_t)(row * 128) + (uint32_t)((c ^ (row & 7)) << 4);
            ldsm4(ah[mt], bA + off);
            ldsm4(al[mt], bAl + off);
        }
        #pragma unroll
        for (int p = 0; p < 4; ++p) {
            int n = wn * 64 + p * 16 + ((lane >> 4) << 3) + (lane & 7);
            int c = k16 * 2 + ((lane >> 3) & 1);
            uint32_t off = (uint32_t)(n * 128) + (uint32_t)((c ^ (n & 7)) << 4);
            uint32_t bh[4], bl[4];
            ldsm4(bh, bB + off);
            ldsm4(bl, bBl + off);
            #pragma unroll
            for (int mt = 0; mt < 4; ++mt) {
                mma16816(acc[mt][2 * p + 0], ah[mt], &bh[0]);
                mma16816(acc[mt][2 * p + 1], ah[mt], &bh[2]);
                mma16816(acc[mt][2 * p + 0], al[mt], &bh[0]);
                mma16816(acc[mt][2 * p + 1], al[mt], &bh[2]);
                mma16816(acc[mt][2 * p + 0], ah[mt], &bl[0]);
                mma16816(acc[mt][2 * p + 1], ah[mt], &bl[2]);
            }
        }
    }
}

__device__ __forceinline__ void tile_ptrs512(int t, int bxm, int bxs,
    const __half* Ahi, const __half* Alo, const __half* Bhi, const __half* Blo,
    int lda, int ldb,
    const __half*& pAh, const __half*& pAl, const __half*& pBh, const __half*& pBl) {
    int by = t >> bxs, bx = t & bxm;
    pAh = Ahi + (size_t)(by * 128) * lda;
    pAl = Alo + (size_t)(by * 128) * lda;
    pBh = Bhi + (size_t)(bx * 256) * ldb;
    pBl = Blo + (size_t)(bx * 256) * ldb;
}

__global__ void __launch_bounds__(256, 1) gemm512p(
    const __half* __restrict__ Ahi, const __half* __restrict__ Alo, int lda,
    const __half* __restrict__ Bhi, const __half* __restrict__ Blo, int ldb,
    int K, int NT, int bxm, int bxs, int mode, float* __restrict__ Cf,
    __half* __restrict__ Chi, __half* __restrict__ Clo, int ldc) {
    extern __shared__ char sm[];
    const int tid = threadIdx.x, lane = tid & 31, wid = tid >> 5;
    const int wm = wid >> 2, wn = wid & 3;
    const int NC = K >> 6;

    // load cursor
    int lt = blockIdx.x, lc = 0, ldbuf = 0;
    const __half *lAh, *lAl, *lBh, *lBl;
    tile_ptrs512(lt, bxm, bxs, Ahi, Alo, Bhi, Blo, lda, ldb, lAh, lAl, lBh, lBl);

    // prologue: 2 chunks
    #pragma unroll
    for (int i = 0; i < 2; ++i) {
        if (lt < NT) {
            load512(sm + ldbuf * STG512, lAh, lAl, lda, lBh, lBl, ldb, lc * 64, tid);
            ldbuf ^= 1;
            if (++lc == NC) {
                lc = 0; lt += gridDim.x;
                if (lt < NT) tile_ptrs512(lt, bxm, bxs, Ahi, Alo, Bhi, Blo, lda, ldb, lAh, lAl, lBh, lBl);
            }
        }
        cp_commit();
    }

    int cbuf = 0;
    for (int t = blockIdx.x; t < NT; t += gridDim.x) {
        float acc[4][8][4];
        #pragma unroll
        for (int a = 0; a < 4; ++a)
            #pragma unroll
            for (int b = 0; b < 8; ++b)
                #pragma unroll
                for (int c = 0; c < 4; ++c) acc[a][b][c] = 0.f;

        for (int c = 0; c < NC; ++c) {
            cp_wait<1>();
            __syncthreads();
            compute512(sm + cbuf * STG512, acc, lane, wm, wn);
            cbuf ^= 1;
            __syncthreads();
            if (lt < NT) {
                load512(sm + ldbuf * STG512, lAh, lAl, lda, lBh, lBl, ldb, lc * 64, tid);
                ldbuf ^= 1;
                if (++lc == NC) {
                    lc = 0; lt += gridDim.x;
                    if (lt < NT) tile_ptrs512(lt, bxm, bxs, Ahi, Alo, Bhi, Blo, lda, ldb, lAh, lAl, lBh, lBl);
                }
            }
            cp_commit();
        }

        // epilogue for tile t (overlaps with in-flight loads of next tile)
        const int rowT = (t >> bxs) * 128, colT = (t & bxm) * 256;
        const int quad = lane >> 2, tc = lane & 3;
        #pragma unroll
        for (int mt = 0; mt < 4; ++mt) {
            #pragma unroll
            for (int h = 0; h < 2; ++h) {
                const int row = rowT + wm * 64 + mt * 16 + quad + h * 8;
                #pragma unroll
                for (int nt = 0; nt < 8; ++nt) {
                    const int col = colT + wn * 64 + nt * 8 + tc * 2;
                    float v0 = acc[mt][nt][h * 2 + 0];
                    float v1 = acc[mt][nt][h * 2 + 1];
                    if (mode == 1) {
                        *(float2*)(Cf + (size_t)row * ldc + col) = make_float2(v0, v1);
                    } else {
                        __half h0 = __float2half_rn(v0), h1 = __float2half_rn(v1);
                        __half l0 = __float2half_rn(v0 - __half2float(h0));
                        __half l1 = __float2half_rn(v1 - __half2float(h1));
                        *(__half2*)(Chi + (size_t)row * ldc + col) = __halves2half2(h0, h1);
                        *(__half2*)(Clo + (size_t)row * ldc + col) = __halves2half2(l0, l1);
                    }
                }
            }
        }
    }
}

// =====================================================================
// O = P @ X^T: tile 128x64, 256 thr (8 warps 4m x 2n, each 32x32),
// BK=64, 4-stage ring, 2 CTAs/SM, grid = 256 CTAs.
// =====================================================================
#define OSTG 24576
#define ONST 4

__device__ __forceinline__ void load_o(char* st, const __half* pA, const __half* pB,
                                       int K, int kc, int tid) {
    const uint32_t b0 = s2u(st);
    #pragma unroll
    for (int i = 0; i < 4; ++i) {             // A: 128x64
        int id = tid + i * 256;
        int r = id >> 3, q = id & 7;
        uint32_t off = (uint32_t)(r * 128) + (uint32_t)((q ^ (r & 7)) << 4);
        cpasync16(b0 + off, pA + (size_t)r * K + kc + q * 8);
    }
    #pragma unroll
    for (int i = 0; i < 2; ++i) {             // B: 64x64
        int id = tid + i * 256;
        int r = id >> 3, q = id & 7;
        uint32_t off = (uint32_t)(r * 128) + (uint32_t)((q ^ (r & 7)) << 4);
        cpasync16(b0 + 16384 + off, pB + (size_t)r * K + kc + q * 8);
    }
}

__global__ void __launch_bounds__(256, 2) gemm_o(
    const __half* __restrict__ A, const __half* __restrict__ B,
    int K, float* __restrict__ Cf, int ldc) {
    extern __shared__ char sm[];
    const int tid = threadIdx.x, lane = tid & 31, wid = tid >> 5;
    const int wm = wid & 3, wn = wid >> 2;
    const int rowA = blockIdx.y * 128, colB = blockIdx.x * 64;
    const __half* pA = A + (size_t)rowA * K;
    const __half* pB = B + (size_t)colB * K;

    float acc[2][4][4];
    #pragma unroll
    for (int a = 0; a < 2; ++a)
        #pragma unroll
        for (int b = 0; b < 4; ++b)
            #pragma unroll
            for (int c = 0; c < 4; ++c) acc[a][b][c] = 0.f;

    const int NC = K >> 6;
    #pragma unroll
    for (int s = 0; s < ONST; ++s) {
        if (s < NC) load_o(sm + s * OSTG, pA, pB, K, s * 64, tid);
        cp_commit();
    }

    for (int c = 0; c < NC; ++c) {
        cp_wait<ONST - 1>();
        __syncthreads();
        char* st = sm + (c % ONST) * OSTG;
        const uint32_t bA = s2u(st), bB = bA + 16384;
        #pragma unroll
        for (int k16 = 0; k16 < 4; ++k16) {
            uint32_t ah[2][4];
            #pragma unroll
            for (int mt = 0; mt < 2; ++mt) {
                int row = wm * 32 + mt * 16 + (lane & 15);
                int cc = k16 * 2 + (lane >> 4);
                uint32_t off = (uint32_t)(row * 128) + (uint32_t)((cc ^ (row & 7)) << 4);
                ldsm4(ah[mt], bA + off);
            }
            #pragma unroll
            for (int p = 0; p < 2; ++p) {
                int n = wn * 32 + p * 16 + ((lane >> 4) << 3) + (lane & 7);
                int cc = k16 * 2 + ((lane >> 3) & 1);
                uint32_t off = (uint32_t)(n * 128) + (uint32_t)((cc ^ (n & 7)) << 4);
                uint32_t bh[4];
                ldsm4(bh, bB + off);
                #pragma unroll
                for (int mt = 0; mt < 2; ++mt) {
                    mma16816(acc[mt][2 * p + 0], ah[mt], &bh[0]);
                    mma16816(acc[mt][2 * p + 1], ah[mt], &bh[2]);
                }
            }
        }
        __syncthreads();
        int nx = c + ONST;
        if (nx < NC) load_o(sm + (nx % ONST) * OSTG, pA, pB, K, nx * 64, tid);
        cp_commit();
    }

    const int quad = lane >> 2, tc = lane & 3;
    #pragma unroll
    for (int mt = 0; mt < 2; ++mt)
        #pragma unroll
        for (int h = 0; h < 2; ++h) {
            const int row = rowA + wm * 32 + mt * 16 + quad + h * 8;
            #pragma unroll
            for (int nt = 0; nt < 4; ++nt) {
                const int col = colB + wn * 32 + nt * 8 + tc * 2;
                *(float2*)(Cf + (size_t)row * ldc + col) =
                    make_float2(acc[mt][nt][h * 2 + 0], acc[mt][nt][h * 2 + 1]);
            }
        }
}

// ---------------- row softmax: Phi = fp16(softmax(L)), vectorized ----------------
__global__ void __launch_bounds__(256) softmax_k() {
    __shared__ float red[256];
    const int row = blockIdx.x;
    const int t = threadIdx.x;
    const float4* Lr = (const float4*)(g_L + (size_t)row * NR);
    float4 v[8];
    float m = -3.4e38f;
    #pragma unroll
    for (int i = 0; i < 8; ++i) {
        v[i] = Lr[t + i * 256];
        m = fmaxf(m, fmaxf(fmaxf(v[i].x, v[i].y), fmaxf(v[i].z, v[i].w)));
    }
    red[t] = m; __syncthreads();
    for (int s = 128; s > 0; s >>= 1) {
        if (t < s) red[t] = fmaxf(red[t], red[t + s]);
        __syncthreads();
    }
    m = red[0]; __syncthreads();
    float sum = 0.f;
    #pragma unroll
    for (int i = 0; i < 8; ++i) {
        v[i].x = __expf(v[i].x - m); v[i].y = __expf(v[i].y - m);
        v[i].z = __expf(v[i].z - m); v[i].w = __expf(v[i].w - m);
        sum += (v[i].x + v[i].y) + (v[i].z + v[i].w);
    }
    red[t] = sum; __syncthreads();
    for (int s = 128; s > 0; s >>= 1) {
        if (t < s) red[t] += red[t + s];
        __syncthreads();
    }
    const float inv = 1.0f / red[0];
    uint2* ph = (uint2*)(g_Phi + (size_t)row * NR);
    #pragma unroll
    for (int i = 0; i < 8; ++i) {
        __half2 a = __floats2half2_rn(v[i].x * inv, v[i].y * inv);
        __half2 b = __floats2half2_rn(v[i].z * inv, v[i].w * inv);
        uint2 w;
        w.x = *(uint32_t*)&a;
        w.y = *(uint32_t*)&b;
        ph[t + i * 256] = w;
    }
}

// ---------------- launch ----------------
extern "C" void kernel_launch(void* const* d_in, const int* in_sizes, int n_in,
                              void* d_out, int out_size) {
    const float* R = (const float*)d_in[0];
    const float* E = (const float*)d_in[1];
    const float* X = (const float*)d_in[2];
    float* out = (float*)d_out;

    const int SMEMW = 2 * STG512;        // 192 KB
    const int SMEMO = ONST * OSTG;       // 96 KB
    cudaFuncSetAttribute(gemm512p, cudaFuncAttributeMaxDynamicSharedMemorySize, SMEMW);
    cudaFuncSetAttribute(gemm_o, cudaFuncAttributeMaxDynamicSharedMemorySize, SMEMO);

    void *xhi, *xlo, *xthi, *whi, *wlo, *qkhi, *qklo, *lptr, *phi;
    cudaGetSymbolAddress(&xhi, g_Xhi);   cudaGetSymbolAddress(&xlo, g_Xlo);
    cudaGetSymbolAddress(&xthi, g_XThi);
    cudaGetSymbolAddress(&whi, g_Whi);   cudaGetSymbolAddress(&wlo, g_Wlo);
    cudaGetSymbolAddress(&qkhi, g_QKhi); cudaGetSymbolAddress(&qklo, g_QKlo);
    cudaGetSymbolAddress(&lptr, g_L);
    cudaGetSymbolAddress(&phi, g_Phi);

    prep_params<<<DD * DD / 256, 256>>>(R, E);
    prep_x<<<NR, 256>>>(X);

    // QK = X @ [R/16 | E]  (split out, ldc=512); 128 tiles (2 x 64)
    gemm512p<<<128, 256, SMEMW>>>((__half*)xhi, (__half*)xlo, DD,
                                  (__half*)whi, (__half*)wlo, DD,
                                  DD, 128, 1, 1, 0, nullptr,
                                  (__half*)qkhi, (__half*)qklo, 512);
    // L = Q @ K^T  (fp32 out); 2048 tiles (32 x 64), persistent 148 CTAs
    gemm512p<<<148, 256, SMEMW>>>((__half*)qkhi, (__half*)qklo, 512,
                                  (__half*)qkhi + 256, (__half*)qklo + 256, 512,
                                  DD, 2048, 31, 5, 1, (float*)lptr,
                                  nullptr, nullptr, NR);
    // P = softmax(L)
    softmax_k<<<NR, 256>>>();
    // O = P @ X  (256 CTAs, 2/SM)
    gemm_o<<<dim3(4, 64), 256, SMEMO>>>((__half*)phi, (__half*)xthi, NR, out, DD);
}